// round 8
// baseline (speedup 1.0000x reference)
#include <cuda_runtime.h>
#include <cstdint>

// Problem: B=4, T=4096, C=384 (n_embd), H=16 (head_size)
// out[b,t,:] = softmax_causal( (x@Wq)(x@Wk)^T / sqrt(H) ) @ (x@Wv)

#define B_     4
#define T_     4096
#define C_     384
#define H_     16
#define BT_    (B_ * T_)
#define SPLITS 8

__device__ float g_q[BT_ * H_];   // pre-scaled by H^-0.5 * log2(e)
__device__ float g_k[BT_ * H_];
__device__ float g_v[BT_ * H_];
__device__ float g_pacc[SPLITS * BT_ * H_];
__device__ float g_pl[SPLITS * BT_];

// ---------------- packed f32x2 helpers ----------------
__device__ __forceinline__ float ex2(float x) {
    float y; asm("ex2.approx.ftz.f32 %0, %1;" : "=f"(y) : "f"(x)); return y;
}
__device__ __forceinline__ double pk2(float lo, float hi) {
    double d; asm("mov.b64 %0, {%1, %2};" : "=d"(d) : "f"(lo), "f"(hi)); return d;
}
__device__ __forceinline__ void upk2(double d, float& lo, float& hi) {
    asm("mov.b64 {%0, %1}, %2;" : "=f"(lo), "=f"(hi) : "d"(d));
}
__device__ __forceinline__ double fma2(double a, double b, double c) {
    double d; asm("fma.rn.f32x2 %0, %1, %2, %3;" : "=d"(d) : "d"(a), "d"(b), "d"(c)); return d;
}
__device__ __forceinline__ double mul2(double a, double b) {
    double d; asm("mul.rn.f32x2 %0, %1, %2;" : "=d"(d) : "d"(a), "d"(b)); return d;
}
__device__ __forceinline__ double add2(double a, double b) {
    double d; asm("add.rn.f32x2 %0, %1, %2;" : "=d"(d) : "d"(a), "d"(b)); return d;
}
__device__ __forceinline__ void cp16(unsigned s, const void* g) {
    asm volatile("cp.async.cg.shared.global [%0], [%1], 16;" :: "r"(s), "l"(g));
}

// ---------------------------------------------------------------------------
// Kernel 1: fused QKV projection.
// Block = 128 threads = 16 rows x 8 C-segments. Grid = 1024 (removes the
// grid-limited occupancy of the 512-block version). x row stride 68 floats
// (16B-aligned, conflict-free). Chunks double-buffered via cp.async;
// partials merged through smem overlay.
// ---------------------------------------------------------------------------
#define PXS 68
#define PXB (16 * PXS * 4)          // 4352 B
#define PWB (3 * 64 * 16 * 4)       // 12288 B
#define PSTAGE (PXB + PWB)          // 16640 B

__global__ __launch_bounds__(128, 4)
void proj_kernel(const float* __restrict__ x,
                 const float* __restrict__ Wk,
                 const float* __restrict__ Wq,
                 const float* __restrict__ Wv) {
    // staging double buffered: 2*16640 = 33280 B; combine overlay: 21504 B
    __shared__ __align__(16) char sbuf[33280];

    const int tid = threadIdx.x;
    const int row = tid & 15;
    const int seg = tid >> 4;        // 0..7
    const long row0 = (long)blockIdx.x * 16;

    double aK[8], aQ[8], aV[8];
#pragma unroll
    for (int i = 0; i < 8; i++) { aK[i] = 0.0; aQ[i] = 0.0; aV[i] = 0.0; }

    const float4* xg = (const float4*)x;   // row stride = 96 float4
    const float4* wg[3] = { (const float4*)Wk, (const float4*)Wq, (const float4*)Wv };

    auto load_chunk = [&](int buf, int cc) {
        unsigned sxa = (unsigned)__cvta_generic_to_shared(sbuf + buf * PSTAGE);
        unsigned swa = sxa + PXB;
        // x tile 16x64: 256 float4; dst row stride 272B (16B-aligned)
        for (int i = tid; i < 256; i += 128) {
            int r = i >> 4, c4 = i & 15;
            cp16(sxa + (unsigned)(r * PXS + c4 * 4) * 4u,
                 xg + (row0 + r) * 96 + cc * 16 + c4);
        }
        // W chunks: 3 x 256 float4, contiguous
        for (int i = tid; i < 768; i += 128) {
            int m = i >> 8, j = i & 255;
            cp16(swa + (unsigned)(m * 256 + j) * 16u, wg[m] + cc * 256 + j);
        }
        asm volatile("cp.async.commit_group;");
    };

    load_chunk(0, 0);

    for (int cc = 0; cc < 6; cc++) {
        const int buf = cc & 1;
        if (cc < 5) {
            load_chunk(buf ^ 1, cc + 1);
            asm volatile("cp.async.wait_group 1;");
        } else {
            asm volatile("cp.async.wait_group 0;");
        }
        __syncthreads();

        const float* sx = (const float*)(sbuf + buf * PSTAGE);
        const float* sw = (const float*)(sbuf + buf * PSTAGE + PXB);

        float xv8[8];
        {
            const float4* xr4 = (const float4*)&sx[row * PXS + seg * 8];
            float4 a = xr4[0], c = xr4[1];
            xv8[0]=a.x; xv8[1]=a.y; xv8[2]=a.z; xv8[3]=a.w;
            xv8[4]=c.x; xv8[5]=c.y; xv8[6]=c.z; xv8[7]=c.w;
        }
        const int cbase = seg * 8;
#pragma unroll
        for (int c = 0; c < 8; c++) {
            double xv2 = pk2(xv8[c], xv8[c]);
            const double2* wk2 = (const double2*)&sw[0 * 1024 + (cbase + c) * 16];
            const double2* wq2 = (const double2*)&sw[1 * 1024 + (cbase + c) * 16];
            const double2* wv2 = (const double2*)&sw[2 * 1024 + (cbase + c) * 16];
#pragma unroll
            for (int m = 0; m < 4; m++) {
                double2 k = wk2[m], q = wq2[m], v = wv2[m];
                aK[2*m+0] = fma2(xv2, k.x, aK[2*m+0]);
                aK[2*m+1] = fma2(xv2, k.y, aK[2*m+1]);
                aQ[2*m+0] = fma2(xv2, q.x, aQ[2*m+0]);
                aQ[2*m+1] = fma2(xv2, q.y, aQ[2*m+1]);
                aV[2*m+0] = fma2(xv2, v.x, aV[2*m+0]);
                aV[2*m+1] = fma2(xv2, v.y, aV[2*m+1]);
            }
        }
        __syncthreads();
    }

    // merge 8 segments: 1..7 publish, 0 accumulates + writes
    double* scomb = (double*)sbuf;   // [7][16][24] = 21504 B
    if (seg != 0) {
        double* d = &scomb[((seg - 1) * 16 + row) * 24];
#pragma unroll
        for (int i = 0; i < 8; i++) {
            d[i] = aK[i]; d[8 + i] = aQ[i]; d[16 + i] = aV[i];
        }
    }
    __syncthreads();
    if (seg == 0) {
        const float qscale = 0.25f * 1.4426950408889634f;  // H^-0.5 * log2(e)
        const double qs2 = pk2(qscale, qscale);
        const long r = row0 + row;
        double* qd = (double*)(g_q + r * 16);
        double* kd = (double*)(g_k + r * 16);
        double* vd = (double*)(g_v + r * 16);
#pragma unroll
        for (int i = 0; i < 8; i++) {
            double k = aK[i], q = aQ[i], v = aV[i];
#pragma unroll
            for (int s = 0; s < 7; s++) {
                const double* d = &scomb[(s * 16 + row) * 24];
                k = add2(k, d[i]); q = add2(q, d[8 + i]); v = add2(v, d[16 + i]);
            }
            kd[i] = k; qd[i] = mul2(q, qs2); vd[i] = v;
        }
    }
}

// ---------------------------------------------------------------------------
// Kernel 2: causal flash attention, split-K partials, Mq=4 with h-split.
// Grid (128, 8, 4). Block = 128 = 8 q-groups x 2 h-halves x 8 key-lanes.
// Each thread: 4 queries, full 16-dim score dot (duplicated across halves),
// but accumulates only 8 of 16 v-dims -> 24 smem bytes per (q,key) pair.
// exp2-domain (no max) => split combining exact. cp.async double-buffered.
// ---------------------------------------------------------------------------
#define KT 64

__global__ __launch_bounds__(128, 3)
void attn_kernel() {
    __shared__ __align__(16) float4 sk4[2][4][KT];
    __shared__ __align__(16) float4 sv4[2][4][KT];

    const int tid = threadIdx.x;
    const int kj  = tid & 7;          // key lane
    const int hh  = (tid >> 3) & 1;   // h-half (v dims hh*8 .. hh*8+7)
    const int qg  = tid >> 4;         // q-group (0..7)
    const int b   = blockIdx.z;
    const int split = blockIdx.y;
    const int tile  = (int)gridDim.x - 1 - (int)blockIdx.x;  // heavy-first
    const int q_start = tile * 32;
    const int gq0 = q_start + qg * 4;

    const int n_keys = q_start + 32;
    const int len = (n_keys + SPLITS - 1) / SPLITS;
    const int kb  = split * len;
    const int ke  = min(kb + len, n_keys);

    double acc[4][4];                 // 4 queries x 8 v-dims (packed)
#pragma unroll
    for (int m = 0; m < 4; m++)
#pragma unroll
        for (int i = 0; i < 4; i++) acc[m][i] = 0.0;
    float l[4] = {0.f, 0.f, 0.f, 0.f};

    if (kb < ke) {
        double q2[4][8];              // full q rows for the dot
#pragma unroll
        for (int m = 0; m < 4; m++) {
            const double2* qsrc = (const double2*)(g_q + ((long)b * T_ + gq0 + m) * 16);
#pragma unroll
            for (int i = 0; i < 4; i++) { double2 t = qsrc[i]; q2[m][2*i] = t.x; q2[m][2*i+1] = t.y; }
        }

        const float4* kg = (const float4*)(g_k + (long)b * T_ * 16);
        const float4* vg = (const float4*)(g_v + (long)b * T_ * 16);

        auto load_tile = [&](int buf, int t0, int nk) {
            for (int i = tid; i < nk * 4; i += 128) {
                int r = i >> 2, c = i & 3;
                cp16((unsigned)__cvta_generic_to_shared(&sk4[buf][c][r]), kg + (long)(t0 + r) * 4 + c);
                cp16((unsigned)__cvta_generic_to_shared(&sv4[buf][c][r]), vg + (long)(t0 + r) * 4 + c);
            }
            asm volatile("cp.async.commit_group;");
        };

        const bool safe = (ke <= q_start);
        const int nt = (ke - kb + KT - 1) / KT;
        load_tile(0, kb, min(KT, ke - kb));

        for (int t = 0; t < nt; t++) {
            const int t0 = kb + t * KT;
            const int nk = min(KT, ke - t0);
            if (t + 1 < nt) {
                load_tile((t + 1) & 1, t0 + KT, min(KT, ke - t0 - KT));
                asm volatile("cp.async.wait_group 1;");
            } else {
                asm volatile("cp.async.wait_group 0;");
            }
            __syncthreads();

            const int buf = t & 1;
#pragma unroll 2
            for (int j = kj; j < nk; j += 8) {
                float4 k0 = sk4[buf][0][j], k1 = sk4[buf][1][j];
                float4 k2 = sk4[buf][2][j], k3 = sk4[buf][3][j];
                double2 K0 = *(double2*)&k0, K1 = *(double2*)&k1;
                double2 K2 = *(double2*)&k2, K3 = *(double2*)&k3;
                float p[4];
#pragma unroll
                for (int m = 0; m < 4; m++) {
                    double sa = mul2(q2[m][0], K0.x);
                    sa = fma2(q2[m][2], K1.x, sa);
                    sa = fma2(q2[m][4], K2.x, sa);
                    sa = fma2(q2[m][6], K3.x, sa);
                    double sb = mul2(q2[m][1], K0.y);
                    sb = fma2(q2[m][3], K1.y, sb);
                    sb = fma2(q2[m][5], K2.y, sb);
                    sb = fma2(q2[m][7], K3.y, sb);
                    float lo, hi; upk2(add2(sa, sb), lo, hi);
                    float e = ex2(lo + hi);
                    p[m] = (safe || (t0 + j <= gq0 + m)) ? e : 0.f;
                    l[m] += p[m];
                }
                // this thread's v half: dims hh*8 .. hh*8+7
                float4 v0 = sv4[buf][2 * hh + 0][j];
                float4 v1 = sv4[buf][2 * hh + 1][j];
                double2 V0 = *(double2*)&v0, V1 = *(double2*)&v1;
#pragma unroll
                for (int m = 0; m < 4; m++) {
                    double p2 = pk2(p[m], p[m]);
                    acc[m][0] = fma2(p2, V0.x, acc[m][0]);
                    acc[m][1] = fma2(p2, V0.y, acc[m][1]);
                    acc[m][2] = fma2(p2, V1.x, acc[m][2]);
                    acc[m][3] = fma2(p2, V1.y, acc[m][3]);
                }
            }
            __syncthreads();
        }
    }

    // reduce across the 8 key-lanes (offsets 1,2,4: stays inside the group)
#pragma unroll
    for (int off = 1; off <= 4; off <<= 1) {
#pragma unroll
        for (int m = 0; m < 4; m++) {
            l[m] += __shfl_xor_sync(0xffffffffu, l[m], off);
#pragma unroll
            for (int i = 0; i < 4; i++)
                acc[m][i] = add2(acc[m][i], __shfl_xor_sync(0xffffffffu, acc[m][i], off));
        }
    }

    if (kj == 0) {
#pragma unroll
        for (int m = 0; m < 4; m++) {
            const long prow = (long)split * BT_ + (long)b * T_ + gq0 + m;
            if (hh == 0) g_pl[prow] = l[m];
            float o[8];
#pragma unroll
            for (int i = 0; i < 4; i++) upk2(acc[m][i], o[2*i], o[2*i+1]);
            float4* p4 = (float4*)(g_pacc + prow * 16 + hh * 8);
            p4[0] = make_float4(o[0], o[1], o[2], o[3]);
            p4[1] = make_float4(o[4], o[5], o[6], o[7]);
        }
    }
}

// ---------------------------------------------------------------------------
// Kernel 3: combine split partials. One thread per output row.
// ---------------------------------------------------------------------------
__global__ __launch_bounds__(256)
void combine_kernel(float* __restrict__ out) {
    const int row = blockIdx.x * 256 + threadIdx.x;
    float l = 0.f;
#pragma unroll
    for (int s = 0; s < SPLITS; s++) l += g_pl[(long)s * BT_ + row];
    const float inv = 1.0f / l;

    float4* o4 = (float4*)out + (long)row * 4;
#pragma unroll
    for (int i = 0; i < 4; i++) {
        float4 a = make_float4(0.f, 0.f, 0.f, 0.f);
#pragma unroll
        for (int s = 0; s < SPLITS; s++) {
            float4 t = ((const float4*)g_pacc)[((long)s * BT_ + row) * 4 + i];
            a.x += t.x; a.y += t.y; a.z += t.z; a.w += t.w;
        }
        o4[i] = make_float4(a.x * inv, a.y * inv, a.z * inv, a.w * inv);
    }
}

extern "C" void kernel_launch(void* const* d_in, const int* in_sizes, int n_in,
                              void* d_out, int out_size) {
    const float* x  = (const float*)d_in[0];
    const float* Wk = (const float*)d_in[1];
    const float* Wq = (const float*)d_in[2];
    const float* Wv = (const float*)d_in[3];
    float* out = (float*)d_out;

    proj_kernel<<<BT_ / 16, 128>>>(x, Wk, Wq, Wv);
    attn_kernel<<<dim3(T_ / 32, SPLITS, B_), 128>>>();
    combine_kernel<<<BT_ / 256, 256>>>(out);
}

// round 9
// speedup vs baseline: 1.0503x; 1.0503x over previous
#include <cuda_runtime.h>
#include <cstdint>

// Problem: B=4, T=4096, C=384 (n_embd), H=16 (head_size)
// out[b,t,:] = softmax_causal( (x@Wq)(x@Wk)^T / sqrt(H) ) @ (x@Wv)

#define B_     4
#define T_     4096
#define C_     384
#define H_     16
#define BT_    (B_ * T_)
#define SPLITS 8

__device__ float g_q[BT_ * H_];   // pre-scaled by H^-0.5 * log2(e)
__device__ float g_k[BT_ * H_];
__device__ float g_v[BT_ * H_];
__device__ float g_pacc[SPLITS * BT_ * H_];
__device__ float g_pl[SPLITS * BT_];

// ---------------- packed f32x2 helpers ----------------
__device__ __forceinline__ float ex2(float x) {
    float y; asm("ex2.approx.ftz.f32 %0, %1;" : "=f"(y) : "f"(x)); return y;
}
__device__ __forceinline__ double pk2(float lo, float hi) {
    double d; asm("mov.b64 %0, {%1, %2};" : "=d"(d) : "f"(lo), "f"(hi)); return d;
}
__device__ __forceinline__ void upk2(double d, float& lo, float& hi) {
    asm("mov.b64 {%0, %1}, %2;" : "=f"(lo), "=f"(hi) : "d"(d));
}
__device__ __forceinline__ double fma2(double a, double b, double c) {
    double d; asm("fma.rn.f32x2 %0, %1, %2, %3;" : "=d"(d) : "d"(a), "d"(b), "d"(c)); return d;
}
__device__ __forceinline__ double mul2(double a, double b) {
    double d; asm("mul.rn.f32x2 %0, %1, %2;" : "=d"(d) : "d"(a), "d"(b)); return d;
}
__device__ __forceinline__ double add2(double a, double b) {
    double d; asm("add.rn.f32x2 %0, %1, %2;" : "=d"(d) : "d"(a), "d"(b)); return d;
}
__device__ __forceinline__ void cp16(unsigned s, const void* g) {
    asm volatile("cp.async.cg.shared.global [%0], [%1], 16;" :: "r"(s), "l"(g));
}

// ---------------------------------------------------------------------------
// Kernel 1: fused QKV projection (R8 version — 29.5 us measured).
// Block = 128 threads = 16 rows x 8 C-segments. Grid = 1024.
// ---------------------------------------------------------------------------
#define PXS 68
#define PXB (16 * PXS * 4)          // 4352 B
#define PWB (3 * 64 * 16 * 4)       // 12288 B
#define PSTAGE (PXB + PWB)          // 16640 B

__global__ __launch_bounds__(128, 4)
void proj_kernel(const float* __restrict__ x,
                 const float* __restrict__ Wk,
                 const float* __restrict__ Wq,
                 const float* __restrict__ Wv) {
    __shared__ __align__(16) char sbuf[33280];

    const int tid = threadIdx.x;
    const int row = tid & 15;
    const int seg = tid >> 4;
    const long row0 = (long)blockIdx.x * 16;

    double aK[8], aQ[8], aV[8];
#pragma unroll
    for (int i = 0; i < 8; i++) { aK[i] = 0.0; aQ[i] = 0.0; aV[i] = 0.0; }

    const float4* xg = (const float4*)x;
    const float4* wg[3] = { (const float4*)Wk, (const float4*)Wq, (const float4*)Wv };

    auto load_chunk = [&](int buf, int cc) {
        unsigned sxa = (unsigned)__cvta_generic_to_shared(sbuf + buf * PSTAGE);
        unsigned swa = sxa + PXB;
        for (int i = tid; i < 256; i += 128) {
            int r = i >> 4, c4 = i & 15;
            cp16(sxa + (unsigned)(r * PXS + c4 * 4) * 4u,
                 xg + (row0 + r) * 96 + cc * 16 + c4);
        }
        for (int i = tid; i < 768; i += 128) {
            int m = i >> 8, j = i & 255;
            cp16(swa + (unsigned)(m * 256 + j) * 16u, wg[m] + cc * 256 + j);
        }
        asm volatile("cp.async.commit_group;");
    };

    load_chunk(0, 0);

    for (int cc = 0; cc < 6; cc++) {
        const int buf = cc & 1;
        if (cc < 5) {
            load_chunk(buf ^ 1, cc + 1);
            asm volatile("cp.async.wait_group 1;");
        } else {
            asm volatile("cp.async.wait_group 0;");
        }
        __syncthreads();

        const float* sx = (const float*)(sbuf + buf * PSTAGE);
        const float* sw = (const float*)(sbuf + buf * PSTAGE + PXB);

        float xv8[8];
        {
            const float4* xr4 = (const float4*)&sx[row * PXS + seg * 8];
            float4 a = xr4[0], c = xr4[1];
            xv8[0]=a.x; xv8[1]=a.y; xv8[2]=a.z; xv8[3]=a.w;
            xv8[4]=c.x; xv8[5]=c.y; xv8[6]=c.z; xv8[7]=c.w;
        }
        const int cbase = seg * 8;
#pragma unroll
        for (int c = 0; c < 8; c++) {
            double xv2 = pk2(xv8[c], xv8[c]);
            const double2* wk2 = (const double2*)&sw[0 * 1024 + (cbase + c) * 16];
            const double2* wq2 = (const double2*)&sw[1 * 1024 + (cbase + c) * 16];
            const double2* wv2 = (const double2*)&sw[2 * 1024 + (cbase + c) * 16];
#pragma unroll
            for (int m = 0; m < 4; m++) {
                double2 k = wk2[m], q = wq2[m], v = wv2[m];
                aK[2*m+0] = fma2(xv2, k.x, aK[2*m+0]);
                aK[2*m+1] = fma2(xv2, k.y, aK[2*m+1]);
                aQ[2*m+0] = fma2(xv2, q.x, aQ[2*m+0]);
                aQ[2*m+1] = fma2(xv2, q.y, aQ[2*m+1]);
                aV[2*m+0] = fma2(xv2, v.x, aV[2*m+0]);
                aV[2*m+1] = fma2(xv2, v.y, aV[2*m+1]);
            }
        }
        __syncthreads();
    }

    double* scomb = (double*)sbuf;   // [7][16][24]
    if (seg != 0) {
        double* d = &scomb[((seg - 1) * 16 + row) * 24];
#pragma unroll
        for (int i = 0; i < 8; i++) {
            d[i] = aK[i]; d[8 + i] = aQ[i]; d[16 + i] = aV[i];
        }
    }
    __syncthreads();
    if (seg == 0) {
        const float qscale = 0.25f * 1.4426950408889634f;
        const double qs2 = pk2(qscale, qscale);
        const long r = row0 + row;
        double* qd = (double*)(g_q + r * 16);
        double* kd = (double*)(g_k + r * 16);
        double* vd = (double*)(g_v + r * 16);
#pragma unroll
        for (int i = 0; i < 8; i++) {
            double k = aK[i], q = aQ[i], v = aV[i];
#pragma unroll
            for (int s = 0; s < 7; s++) {
                const double* d = &scomb[(s * 16 + row) * 24];
                k = add2(k, d[i]); q = add2(q, d[8 + i]); v = add2(v, d[16 + i]);
            }
            kd[i] = k; qd[i] = mul2(q, qs2); vd[i] = v;
        }
    }
}

// ---------------------------------------------------------------------------
// Kernel 2: causal flash attention, split-K partials, Mq=2 (R7 core).
// Grid (128, 8, 4). Block = 128 = 16 q-slots x 8 key-lanes, 2 queries/thread.
// Per-TILE causality: only the final diagonal tile runs the predicated loop;
// all other tiles use the select-free fast loop.
// ---------------------------------------------------------------------------
#define KT 64

__global__ __launch_bounds__(128, 4)
void attn_kernel() {
    __shared__ __align__(16) float4 sk4[2][4][KT];
    __shared__ __align__(16) float4 sv4[2][4][KT];

    const int tid = threadIdx.x;
    const int kj  = tid & 7;
    const int qs  = tid >> 3;
    const int b   = blockIdx.z;
    const int split = blockIdx.y;
    const int tile  = (int)gridDim.x - 1 - (int)blockIdx.x;  // heavy-first
    const int q_start = tile * 32;
    const int gq0 = q_start + qs * 2;

    const int n_keys = q_start + 32;
    const int len = (n_keys + SPLITS - 1) / SPLITS;
    const int kb  = split * len;
    const int ke  = min(kb + len, n_keys);

    double acc[2][8];
#pragma unroll
    for (int m = 0; m < 2; m++)
#pragma unroll
        for (int i = 0; i < 8; i++) acc[m][i] = 0.0;
    float l[2] = {0.f, 0.f};

    if (kb < ke) {
        double q2[2][8];
#pragma unroll
        for (int m = 0; m < 2; m++) {
            const double2* qsrc = (const double2*)(g_q + ((long)b * T_ + gq0 + m) * 16);
#pragma unroll
            for (int i = 0; i < 4; i++) { double2 t = qsrc[i]; q2[m][2*i] = t.x; q2[m][2*i+1] = t.y; }
        }

        const float4* kg = (const float4*)(g_k + (long)b * T_ * 16);
        const float4* vg = (const float4*)(g_v + (long)b * T_ * 16);

        auto load_tile = [&](int buf, int t0, int nk) {
            for (int i = tid; i < nk * 4; i += 128) {
                int r = i >> 2, c = i & 3;
                cp16((unsigned)__cvta_generic_to_shared(&sk4[buf][c][r]), kg + (long)(t0 + r) * 4 + c);
                cp16((unsigned)__cvta_generic_to_shared(&sv4[buf][c][r]), vg + (long)(t0 + r) * 4 + c);
            }
            asm volatile("cp.async.commit_group;");
        };

        const int nt = (ke - kb + KT - 1) / KT;
        load_tile(0, kb, min(KT, ke - kb));

        for (int t = 0; t < nt; t++) {
            const int t0 = kb + t * KT;
            const int nk = min(KT, ke - t0);
            if (t + 1 < nt) {
                load_tile((t + 1) & 1, t0 + KT, min(KT, ke - t0 - KT));
                asm volatile("cp.async.wait_group 1;");
            } else {
                asm volatile("cp.async.wait_group 0;");
            }
            __syncthreads();

            const int buf = t & 1;
            if (t0 + nk <= q_start + 1) {
                // fast path: every key in tile valid for every query in block
#pragma unroll 2
                for (int j = kj; j < nk; j += 8) {
                    float4 k0 = sk4[buf][0][j], k1 = sk4[buf][1][j];
                    float4 k2 = sk4[buf][2][j], k3 = sk4[buf][3][j];
                    double2 K0 = *(double2*)&k0, K1 = *(double2*)&k1;
                    double2 K2 = *(double2*)&k2, K3 = *(double2*)&k3;
                    float p[2];
#pragma unroll
                    for (int m = 0; m < 2; m++) {
                        double sa = mul2(q2[m][0], K0.x);
                        sa = fma2(q2[m][2], K1.x, sa);
                        sa = fma2(q2[m][4], K2.x, sa);
                        sa = fma2(q2[m][6], K3.x, sa);
                        double sb = mul2(q2[m][1], K0.y);
                        sb = fma2(q2[m][3], K1.y, sb);
                        sb = fma2(q2[m][5], K2.y, sb);
                        sb = fma2(q2[m][7], K3.y, sb);
                        float lo, hi; upk2(add2(sa, sb), lo, hi);
                        p[m] = ex2(lo + hi);
                        l[m] += p[m];
                    }
                    float4 v0 = sv4[buf][0][j], v1 = sv4[buf][1][j];
                    float4 v2 = sv4[buf][2][j], v3 = sv4[buf][3][j];
                    double2 V0 = *(double2*)&v0, V1 = *(double2*)&v1;
                    double2 V2 = *(double2*)&v2, V3 = *(double2*)&v3;
#pragma unroll
                    for (int m = 0; m < 2; m++) {
                        double p2 = pk2(p[m], p[m]);
                        acc[m][0] = fma2(p2, V0.x, acc[m][0]);
                        acc[m][1] = fma2(p2, V0.y, acc[m][1]);
                        acc[m][2] = fma2(p2, V1.x, acc[m][2]);
                        acc[m][3] = fma2(p2, V1.y, acc[m][3]);
                        acc[m][4] = fma2(p2, V2.x, acc[m][4]);
                        acc[m][5] = fma2(p2, V2.y, acc[m][5]);
                        acc[m][6] = fma2(p2, V3.x, acc[m][6]);
                        acc[m][7] = fma2(p2, V3.y, acc[m][7]);
                    }
                }
            } else {
                // diagonal tile: per-pair causal predicate
#pragma unroll 2
                for (int j = kj; j < nk; j += 8) {
                    const int key = t0 + j;
                    float4 k0 = sk4[buf][0][j], k1 = sk4[buf][1][j];
                    float4 k2 = sk4[buf][2][j], k3 = sk4[buf][3][j];
                    double2 K0 = *(double2*)&k0, K1 = *(double2*)&k1;
                    double2 K2 = *(double2*)&k2, K3 = *(double2*)&k3;
                    float p[2];
#pragma unroll
                    for (int m = 0; m < 2; m++) {
                        double sa = mul2(q2[m][0], K0.x);
                        sa = fma2(q2[m][2], K1.x, sa);
                        sa = fma2(q2[m][4], K2.x, sa);
                        sa = fma2(q2[m][6], K3.x, sa);
                        double sb = mul2(q2[m][1], K0.y);
                        sb = fma2(q2[m][3], K1.y, sb);
                        sb = fma2(q2[m][5], K2.y, sb);
                        sb = fma2(q2[m][7], K3.y, sb);
                        float lo, hi; upk2(add2(sa, sb), lo, hi);
                        float e = ex2(lo + hi);
                        p[m] = (key <= gq0 + m) ? e : 0.f;
                        l[m] += p[m];
                    }
                    float4 v0 = sv4[buf][0][j], v1 = sv4[buf][1][j];
                    float4 v2 = sv4[buf][2][j], v3 = sv4[buf][3][j];
                    double2 V0 = *(double2*)&v0, V1 = *(double2*)&v1;
                    double2 V2 = *(double2*)&v2, V3 = *(double2*)&v3;
#pragma unroll
                    for (int m = 0; m < 2; m++) {
                        double p2 = pk2(p[m], p[m]);
                        acc[m][0] = fma2(p2, V0.x, acc[m][0]);
                        acc[m][1] = fma2(p2, V0.y, acc[m][1]);
                        acc[m][2] = fma2(p2, V1.x, acc[m][2]);
                        acc[m][3] = fma2(p2, V1.y, acc[m][3]);
                        acc[m][4] = fma2(p2, V2.x, acc[m][4]);
                        acc[m][5] = fma2(p2, V2.y, acc[m][5]);
                        acc[m][6] = fma2(p2, V3.x, acc[m][6]);
                        acc[m][7] = fma2(p2, V3.y, acc[m][7]);
                    }
                }
            }
            __syncthreads();
        }
    }

    // reduce across the 8 key-lanes of each q-slot
#pragma unroll
    for (int off = 1; off <= 4; off <<= 1) {
#pragma unroll
        for (int m = 0; m < 2; m++) {
            l[m] += __shfl_xor_sync(0xffffffffu, l[m], off);
#pragma unroll
            for (int i = 0; i < 8; i++)
                acc[m][i] = add2(acc[m][i], __shfl_xor_sync(0xffffffffu, acc[m][i], off));
        }
    }

    if (kj == 0) {
#pragma unroll
        for (int m = 0; m < 2; m++) {
            const long prow = (long)split * BT_ + (long)b * T_ + gq0 + m;
            g_pl[prow] = l[m];
            float o[16];
#pragma unroll
            for (int i = 0; i < 8; i++) upk2(acc[m][i], o[2*i], o[2*i+1]);
            float4* p4 = (float4*)(g_pacc + prow * 16);
#pragma unroll
            for (int i = 0; i < 4; i++)
                p4[i] = make_float4(o[4*i+0], o[4*i+1], o[4*i+2], o[4*i+3]);
        }
    }
}

// ---------------------------------------------------------------------------
// Kernel 3: combine split partials. One thread per output row.
// ---------------------------------------------------------------------------
__global__ __launch_bounds__(256)
void combine_kernel(float* __restrict__ out) {
    const int row = blockIdx.x * 256 + threadIdx.x;
    float l = 0.f;
#pragma unroll
    for (int s = 0; s < SPLITS; s++) l += g_pl[(long)s * BT_ + row];
    const float inv = 1.0f / l;

    float4* o4 = (float4*)out + (long)row * 4;
#pragma unroll
    for (int i = 0; i < 4; i++) {
        float4 a = make_float4(0.f, 0.f, 0.f, 0.f);
#pragma unroll
        for (int s = 0; s < SPLITS; s++) {
            float4 t = ((const float4*)g_pacc)[((long)s * BT_ + row) * 4 + i];
            a.x += t.x; a.y += t.y; a.z += t.z; a.w += t.w;
        }
        o4[i] = make_float4(a.x * inv, a.y * inv, a.z * inv, a.w * inv);
    }
}

extern "C" void kernel_launch(void* const* d_in, const int* in_sizes, int n_in,
                              void* d_out, int out_size) {
    const float* x  = (const float*)d_in[0];
    const float* Wk = (const float*)d_in[1];
    const float* Wq = (const float*)d_in[2];
    const float* Wv = (const float*)d_in[3];
    float* out = (float*)d_out;

    proj_kernel<<<BT_ / 16, 128>>>(x, Wk, Wq, Wv);
    attn_kernel<<<dim3(T_ / 32, SPLITS, B_), 128>>>();
    combine_kernel<<<BT_ / 256, 256>>>(out);
}

// round 10
// speedup vs baseline: 1.7508x; 1.6669x over previous
#include <cuda_runtime.h>
#include <cuda_fp16.h>
#include <cstdint>

// Problem: B=4, T=4096, C=384 (n_embd), H=16 (head_size)
// out[b,t,:] = softmax_causal( (x@Wq)(x@Wk)^T / sqrt(H) ) @ (x@Wv)

#define B_     4
#define T_     4096
#define C_     384
#define H_     16
#define BT_    (B_ * T_)
#define SPLITS 8
#define NSLOT  (SPLITS * 4)      // 8 splits x 4 warps

// fp16 hi/lo planes. q pre-scaled by H^-0.5 * log2(e). q,k: [token][16h].
// v: [b][h][t] (transposed, for coalesced cp.async of key ranges).
__device__ uint4 g_qh_[BT_ * 2];
__device__ uint4 g_ql_[BT_ * 2];
__device__ uint4 g_kh_[BT_ * 2];
__device__ uint4 g_kl_[BT_ * 2];
__device__ uint4 g_vh_[B_ * 16 * T_ / 8];
__device__ uint4 g_vl_[B_ * 16 * T_ / 8];
__device__ float g_pacc[(size_t)NSLOT * BT_ * H_];
__device__ float g_pl[NSLOT * BT_];

// ---------------- helpers ----------------
__device__ __forceinline__ float ex2(float x) {
    float y; asm("ex2.approx.ftz.f32 %0, %1;" : "=f"(y) : "f"(x)); return y;
}
__device__ __forceinline__ double pk2(float lo, float hi) {
    double d; asm("mov.b64 %0, {%1, %2};" : "=d"(d) : "f"(lo), "f"(hi)); return d;
}
__device__ __forceinline__ void upk2(double d, float& lo, float& hi) {
    asm("mov.b64 {%0, %1}, %2;" : "=f"(lo), "=f"(hi) : "d"(d));
}
__device__ __forceinline__ double fma2(double a, double b, double c) {
    double d; asm("fma.rn.f32x2 %0, %1, %2, %3;" : "=d"(d) : "d"(a), "d"(b), "d"(c)); return d;
}
__device__ __forceinline__ double mul2(double a, double b) {
    double d; asm("mul.rn.f32x2 %0, %1, %2;" : "=d"(d) : "d"(a), "d"(b)); return d;
}
__device__ __forceinline__ double add2(double a, double b) {
    double d; asm("add.rn.f32x2 %0, %1, %2;" : "=d"(d) : "d"(a), "d"(b)); return d;
}
__device__ __forceinline__ void cp16(unsigned s, const void* g) {
    asm volatile("cp.async.cg.shared.global [%0], [%1], 16;" :: "r"(s), "l"(g));
}
// pack two f32 -> f16x2 (lo = first/lower element)
__device__ __forceinline__ unsigned packh2(float hi, float lo) {
    unsigned r; asm("cvt.rn.f16x2.f32 %0, %1, %2;" : "=r"(r) : "f"(hi), "f"(lo)); return r;
}
__device__ __forceinline__ unsigned pack2h(__half a, __half b) {  // a = lower
    return (unsigned)__half_as_ushort(a) | ((unsigned)__half_as_ushort(b) << 16);
}
__device__ __forceinline__ void split16(float x, __half& hi, __half& lo) {
    hi = __float2half_rn(x);
    lo = __float2half_rn(x - __half2float(hi));
}
// D = A(16x16 f16) * B(16x8 f16) + D, f32 accum
__device__ __forceinline__ void mma16816(float* d, const unsigned* a, const unsigned* b) {
    asm volatile(
        "mma.sync.aligned.m16n8k16.row.col.f32.f16.f16.f32 "
        "{%0,%1,%2,%3}, {%4,%5,%6,%7}, {%8,%9}, {%0,%1,%2,%3};"
        : "+f"(d[0]), "+f"(d[1]), "+f"(d[2]), "+f"(d[3])
        : "r"(a[0]), "r"(a[1]), "r"(a[2]), "r"(a[3]), "r"(b[0]), "r"(b[1]));
}

// ---------------------------------------------------------------------------
// Kernel 1: fused QKV projection (R8 core, new split-fp16 epilogue).
// Block = 128 threads = 16 rows x 8 C-segments. Grid = 1024.
// ---------------------------------------------------------------------------
#define PXS 68
#define PXB (16 * PXS * 4)
#define PWB (3 * 64 * 16 * 4)
#define PSTAGE (PXB + PWB)

__global__ __launch_bounds__(128, 4)
void proj_kernel(const float* __restrict__ x,
                 const float* __restrict__ Wk,
                 const float* __restrict__ Wq,
                 const float* __restrict__ Wv) {
    __shared__ __align__(16) char sbuf[33280];

    const int tid = threadIdx.x;
    const int row = tid & 15;
    const int seg = tid >> 4;
    const long row0 = (long)blockIdx.x * 16;

    double aK[8], aQ[8], aV[8];
#pragma unroll
    for (int i = 0; i < 8; i++) { aK[i] = 0.0; aQ[i] = 0.0; aV[i] = 0.0; }

    const float4* xg = (const float4*)x;
    const float4* wg[3] = { (const float4*)Wk, (const float4*)Wq, (const float4*)Wv };

    auto load_chunk = [&](int buf, int cc) {
        unsigned sxa = (unsigned)__cvta_generic_to_shared(sbuf + buf * PSTAGE);
        unsigned swa = sxa + PXB;
        for (int i = tid; i < 256; i += 128) {
            int r = i >> 4, c4 = i & 15;
            cp16(sxa + (unsigned)(r * PXS + c4 * 4) * 4u,
                 xg + (row0 + r) * 96 + cc * 16 + c4);
        }
        for (int i = tid; i < 768; i += 128) {
            int m = i >> 8, j = i & 255;
            cp16(swa + (unsigned)(m * 256 + j) * 16u, wg[m] + cc * 256 + j);
        }
        asm volatile("cp.async.commit_group;");
    };

    load_chunk(0, 0);

    for (int cc = 0; cc < 6; cc++) {
        const int buf = cc & 1;
        if (cc < 5) {
            load_chunk(buf ^ 1, cc + 1);
            asm volatile("cp.async.wait_group 1;");
        } else {
            asm volatile("cp.async.wait_group 0;");
        }
        __syncthreads();

        const float* sx = (const float*)(sbuf + buf * PSTAGE);
        const float* sw = (const float*)(sbuf + buf * PSTAGE + PXB);

        float xv8[8];
        {
            const float4* xr4 = (const float4*)&sx[row * PXS + seg * 8];
            float4 a = xr4[0], c = xr4[1];
            xv8[0]=a.x; xv8[1]=a.y; xv8[2]=a.z; xv8[3]=a.w;
            xv8[4]=c.x; xv8[5]=c.y; xv8[6]=c.z; xv8[7]=c.w;
        }
        const int cbase = seg * 8;
#pragma unroll
        for (int c = 0; c < 8; c++) {
            double xv2 = pk2(xv8[c], xv8[c]);
            const double2* wk2 = (const double2*)&sw[0 * 1024 + (cbase + c) * 16];
            const double2* wq2 = (const double2*)&sw[1 * 1024 + (cbase + c) * 16];
            const double2* wv2 = (const double2*)&sw[2 * 1024 + (cbase + c) * 16];
#pragma unroll
            for (int m = 0; m < 4; m++) {
                double2 k = wk2[m], q = wq2[m], v = wv2[m];
                aK[2*m+0] = fma2(xv2, k.x, aK[2*m+0]);
                aK[2*m+1] = fma2(xv2, k.y, aK[2*m+1]);
                aQ[2*m+0] = fma2(xv2, q.x, aQ[2*m+0]);
                aQ[2*m+1] = fma2(xv2, q.y, aQ[2*m+1]);
                aV[2*m+0] = fma2(xv2, v.x, aV[2*m+0]);
                aV[2*m+1] = fma2(xv2, v.y, aV[2*m+1]);
            }
        }
        __syncthreads();
    }

    double* scomb = (double*)sbuf;   // [7][16][24]
    if (seg != 0) {
        double* d = &scomb[((seg - 1) * 16 + row) * 24];
#pragma unroll
        for (int i = 0; i < 8; i++) {
            d[i] = aK[i]; d[8 + i] = aQ[i]; d[16 + i] = aV[i];
        }
    }
    __syncthreads();
    if (seg == 0) {
        const float qscale = 0.25f * 1.4426950408889634f;  // H^-0.5 * log2(e)
        const double qs2 = pk2(qscale, qscale);
        float kf[16], qf[16], vf[16];
#pragma unroll
        for (int i = 0; i < 8; i++) {
            double k = aK[i], q = aQ[i], v = aV[i];
#pragma unroll
            for (int s = 0; s < 7; s++) {
                const double* d = &scomb[(s * 16 + row) * 24];
                k = add2(k, d[i]); q = add2(q, d[8 + i]); v = add2(v, d[16 + i]);
            }
            q = mul2(q, qs2);
            upk2(k, kf[2*i], kf[2*i+1]);
            upk2(q, qf[2*i], qf[2*i+1]);
            upk2(v, vf[2*i], vf[2*i+1]);
        }

        const long r = row0 + row;
        const int bb = (int)(r >> 12);
        const int tt = (int)(r & (T_ - 1));

        unsigned uqh[8], uql[8], ukh[8], ukl[8];
#pragma unroll
        for (int i = 0; i < 8; i++) {
            __half h0, l0, h1, l1;
            split16(qf[2*i], h0, l0); split16(qf[2*i+1], h1, l1);
            uqh[i] = pack2h(h0, h1); uql[i] = pack2h(l0, l1);
            split16(kf[2*i], h0, l0); split16(kf[2*i+1], h1, l1);
            ukh[i] = pack2h(h0, h1); ukl[i] = pack2h(l0, l1);
        }
        g_qh_[r*2+0] = make_uint4(uqh[0],uqh[1],uqh[2],uqh[3]);
        g_qh_[r*2+1] = make_uint4(uqh[4],uqh[5],uqh[6],uqh[7]);
        g_ql_[r*2+0] = make_uint4(uql[0],uql[1],uql[2],uql[3]);
        g_ql_[r*2+1] = make_uint4(uql[4],uql[5],uql[6],uql[7]);
        g_kh_[r*2+0] = make_uint4(ukh[0],ukh[1],ukh[2],ukh[3]);
        g_kh_[r*2+1] = make_uint4(ukh[4],ukh[5],ukh[6],ukh[7]);
        g_kl_[r*2+0] = make_uint4(ukl[0],ukl[1],ukl[2],ukl[3]);
        g_kl_[r*2+1] = make_uint4(ukl[4],ukl[5],ukl[6],ukl[7]);

        __half* vh = (__half*)g_vh_;
        __half* vl = (__half*)g_vl_;
#pragma unroll
        for (int i = 0; i < 16; i++) {
            __half h0, l0; split16(vf[i], h0, l0);
            vh[(size_t)(bb * 16 + i) * T_ + tt] = h0;
            vl[(size_t)(bb * 16 + i) * T_ + tt] = l0;
        }
    }
}

// ---------------------------------------------------------------------------
// Kernel 2: causal flash attention on tensor cores (mma.sync m16n8k16 fp16,
// hi/lo split operands, fp32 accum). Grid (128, 8, 4); block = 4 warps.
// Each warp covers every 4th 16-key chunk of its split with its own
// double-buffered cp.async pipeline, writing partial (acc, l) to slot
// split*4+warp. exp2-domain => exact split combining.
// ---------------------------------------------------------------------------
__global__ __launch_bounds__(128, 4)
void attn_kernel() {
    // per warp: 2 bufs x (khi 768 | klo 768 | vhi 768 | vlo 768) = 6144 B
    __shared__ __align__(16) char sbuf[4 * 6144];

    const int tid  = threadIdx.x;
    const int w    = tid >> 5;
    const int lane = tid & 31;
    const int g    = lane >> 2;    // groupID (0..7)
    const int tig  = lane & 3;     // thread-in-group
    const int b    = blockIdx.z;
    const int split = blockIdx.y;
    const int tile  = (int)gridDim.x - 1 - (int)blockIdx.x;  // heavy-first
    const int q_start = tile * 32;
    const int n_keys = q_start + 32;
    const int len = ((n_keys + 127) >> 7) << 4;   // 16-aligned split length
    const int kb  = split * len;
    const int ke  = min(kb + len, n_keys);

    // Q fragments (A of m16n8k16): a0(r,2c) a1(r+8,2c) a2(r,2c+8) a3(r+8,2c+8)
    unsigned qh[2][4], ql[2][4];
    {
        const char* qhb = (const char*)g_qh_;
        const char* qlb = (const char*)g_ql_;
        const size_t qrow0 = (size_t)b * T_ + q_start;
#pragma unroll
        for (int mt = 0; mt < 2; mt++)
#pragma unroll
            for (int p4 = 0; p4 < 4; p4++) {
                int roff = mt * 16 + g + ((p4 & 1) << 3);
                int hoff = tig * 2 + ((p4 >> 1) << 3);
                size_t off = (qrow0 + roff) * 32 + hoff * 2;
                qh[mt][p4] = *(const unsigned*)(qhb + off);
                ql[mt][p4] = *(const unsigned*)(qlb + off);
            }
    }

    float Do[2][2][4];
#pragma unroll
    for (int a = 0; a < 2; a++)
#pragma unroll
        for (int c = 0; c < 2; c++)
#pragma unroll
            for (int e = 0; e < 4; e++) Do[a][c][e] = 0.f;
    float l[2][2] = {{0.f, 0.f}, {0.f, 0.f}};

    char* wb = sbuf + w * 6144;
    const __half* khg = (const __half*)g_kh_ + (size_t)b * T_ * 16;
    const __half* klg = (const __half*)g_kl_ + (size_t)b * T_ * 16;
    const __half* vhg = (const __half*)g_vh_ + (size_t)b * 16 * T_;
    const __half* vlg = (const __half*)g_vl_ + (size_t)b * 16 * T_;

    auto load_chunk = [&](int bf, int t0) {
        unsigned sa = (unsigned)__cvta_generic_to_shared(wb + bf * 3072);
        const int e = lane >> 1;      // key (k) or h (v), 0..15
        const int hf = lane & 1;      // which 16B half of the 32B row
        cp16(sa +        (unsigned)(e * 48 + hf * 16), khg + (size_t)(t0 + e) * 16 + hf * 8);
        cp16(sa + 768u  + (unsigned)(e * 48 + hf * 16), klg + (size_t)(t0 + e) * 16 + hf * 8);
        cp16(sa + 1536u + (unsigned)(e * 48 + hf * 16), vhg + (size_t)e * T_ + t0 + hf * 8);
        cp16(sa + 2304u + (unsigned)(e * 48 + hf * 16), vlg + (size_t)e * T_ + t0 + hf * 8);
        asm volatile("cp.async.commit_group;");
    };

    auto compute = [&](int bf, int t0, bool masked) {
        const char* kh_s = wb + bf * 3072;
        const char* kl_s = kh_s + 768;
        const char* vh_s = kh_s + 1536;
        const char* vl_s = kh_s + 2304;

        // B fragments: scores (K^T): b0 rows h=2c..2c+1, col key=g+nt*8
        unsigned khb[2][2], klb[2][2], vhb[2][2], vlb[2][2];
#pragma unroll
        for (int nt = 0; nt < 2; nt++) {
            int key = g + nt * 8;
            khb[nt][0] = *(const unsigned*)(kh_s + key * 48 + tig * 4);
            khb[nt][1] = *(const unsigned*)(kh_s + key * 48 + 16 + tig * 4);
            klb[nt][0] = *(const unsigned*)(kl_s + key * 48 + tig * 4);
            klb[nt][1] = *(const unsigned*)(kl_s + key * 48 + 16 + tig * 4);
            int h = g + nt * 8;   // PV: b0 rows key=2c..2c+1 (+16B for +8), col h
            vhb[nt][0] = *(const unsigned*)(vh_s + h * 48 + tig * 4);
            vhb[nt][1] = *(const unsigned*)(vh_s + h * 48 + 16 + tig * 4);
            vlb[nt][0] = *(const unsigned*)(vl_s + h * 48 + tig * 4);
            vlb[nt][1] = *(const unsigned*)(vl_s + h * 48 + 16 + tig * 4);
        }

#pragma unroll
        for (int mt = 0; mt < 2; mt++) {
            float ds[2][4];
#pragma unroll
            for (int nt = 0; nt < 2; nt++) {
#pragma unroll
                for (int e = 0; e < 4; e++) ds[nt][e] = 0.f;
                mma16816(ds[nt], qh[mt], khb[nt]);
                mma16816(ds[nt], qh[mt], klb[nt]);
                mma16816(ds[nt], ql[mt], khb[nt]);
            }
            // softmax-exp + causal mask + row sums
            const int rowq0 = q_start + mt * 16 + g;   // rows rowq0, rowq0+8
#pragma unroll
            for (int nt = 0; nt < 2; nt++) {
                const int kc = t0 + nt * 8 + 2 * tig;
#pragma unroll
                for (int e = 0; e < 4; e++) {
                    float p = ex2(ds[nt][e]);
                    if (masked) {
                        int key = kc + (e & 1);
                        int rq  = rowq0 + ((e >> 1) << 3);
                        p = (key <= rq) ? p : 0.f;
                    }
                    ds[nt][e] = p;
                    l[mt][e >> 1] += p;
                }
            }
            // P fragment = D layout directly (cvt only)
            unsigned pa[4];
            pa[0] = packh2(ds[0][1], ds[0][0]);
            pa[1] = packh2(ds[0][3], ds[0][2]);
            pa[2] = packh2(ds[1][1], ds[1][0]);
            pa[3] = packh2(ds[1][3], ds[1][2]);
#pragma unroll
            for (int nh = 0; nh < 2; nh++) {
                mma16816(Do[mt][nh], pa, vhb[nh]);
                mma16816(Do[mt][nh], pa, vlb[nh]);
            }
        }
    };

    int t0 = kb + w * 16;
    if (t0 < ke) {
        load_chunk(0, t0);
        int bf = 0;
        while (t0 < ke) {
            int tn = t0 + 64;   // this warp's next chunk (stride 4 chunks)
            if (tn < ke) {
                load_chunk(bf ^ 1, tn);
                asm volatile("cp.async.wait_group 1;");
            } else {
                asm volatile("cp.async.wait_group 0;");
            }
            __syncwarp();
            compute(bf, t0, t0 >= q_start);
            __syncwarp();
            bf ^= 1; t0 = tn;
        }
    }

    // reduce row sums over the quad (cols live in tig)
#pragma unroll
    for (int off = 1; off <= 2; off <<= 1)
#pragma unroll
        for (int mt = 0; mt < 2; mt++) {
            l[mt][0] += __shfl_xor_sync(0xffffffffu, l[mt][0], off);
            l[mt][1] += __shfl_xor_sync(0xffffffffu, l[mt][1], off);
        }

    // write partial numerators + denominators to slot (split*4 + w)
    const size_t slotBase = (size_t)(split * 4 + w) * BT_ + (size_t)b * T_;
#pragma unroll
    for (int mt = 0; mt < 2; mt++) {
        const size_t r0 = slotBase + q_start + mt * 16 + g;
        if (tig == 0) {
            g_pl[r0]     = l[mt][0];
            g_pl[r0 + 8] = l[mt][1];
        }
#pragma unroll
        for (int nt = 0; nt < 2; nt++) {
            float2* p0 = (float2*)(g_pacc + r0 * 16 + nt * 8 + tig * 2);
            float2* p1 = (float2*)(g_pacc + (r0 + 8) * 16 + nt * 8 + tig * 2);
            *p0 = make_float2(Do[mt][nt][0], Do[mt][nt][1]);
            *p1 = make_float2(Do[mt][nt][2], Do[mt][nt][3]);
        }
    }
}

// ---------------------------------------------------------------------------
// Kernel 3: combine 32 partial slots. One thread per output row.
// ---------------------------------------------------------------------------
__global__ __launch_bounds__(256)
void combine_kernel(float* __restrict__ out) {
    const int row = blockIdx.x * 256 + threadIdx.x;
    float l = 0.f;
#pragma unroll 8
    for (int s = 0; s < NSLOT; s++) l += g_pl[(size_t)s * BT_ + row];
    const float inv = 1.0f / l;

    float4 a[4];
#pragma unroll
    for (int i = 0; i < 4; i++) a[i] = make_float4(0.f, 0.f, 0.f, 0.f);
#pragma unroll 4
    for (int s = 0; s < NSLOT; s++) {
        const float4* p = (const float4*)(g_pacc + ((size_t)s * BT_ + row) * 16);
#pragma unroll
        for (int i = 0; i < 4; i++) {
            float4 t = p[i];
            a[i].x += t.x; a[i].y += t.y; a[i].z += t.z; a[i].w += t.w;
        }
    }
    float4* o4 = (float4*)out + (size_t)row * 4;
#pragma unroll
    for (int i = 0; i < 4; i++)
        o4[i] = make_float4(a[i].x * inv, a[i].y * inv, a[i].z * inv, a[i].w * inv);
}

extern "C" void kernel_launch(void* const* d_in, const int* in_sizes, int n_in,
                              void* d_out, int out_size) {
    const float* x  = (const float*)d_in[0];
    const float* Wk = (const float*)d_in[1];
    const float* Wq = (const float*)d_in[2];
    const float* Wv = (const float*)d_in[3];
    float* out = (float*)d_out;

    proj_kernel<<<BT_ / 16, 128>>>(x, Wk, Wq, Wv);
    attn_kernel<<<dim3(T_ / 32, SPLITS, B_), 128>>>();
    combine_kernel<<<BT_ / 256, 256>>>(out);
}

// round 11
// speedup vs baseline: 2.0106x; 1.1484x over previous
#include <cuda_runtime.h>
#include <cuda_fp16.h>
#include <cstdint>

// Problem: B=4, T=4096, C=384 (n_embd), H=16 (head_size)
// out[b,t,:] = softmax_causal( (x@Wq)(x@Wk)^T / sqrt(H) ) @ (x@Wv)

#define B_     4
#define T_     4096
#define C_     384
#define H_     16
#define BT_    (B_ * T_)
#define SPLITS 8

// fp16 hi/lo planes. q pre-scaled by H^-0.5 * log2(e). q,k: [token][16h].
// v: [b][h][t] (transposed, for coalesced cp.async of key ranges).
__device__ uint4 g_qh_[BT_ * 2];
__device__ uint4 g_ql_[BT_ * 2];
__device__ uint4 g_kh_[BT_ * 2];
__device__ uint4 g_kl_[BT_ * 2];
__device__ uint4 g_vh_[B_ * 16 * T_ / 8];
__device__ uint4 g_vl_[B_ * 16 * T_ / 8];
__device__ float g_pacc[(size_t)SPLITS * BT_ * H_];   // block-reduced partials
__device__ float g_pl[SPLITS * BT_];

// ---------------- helpers ----------------
__device__ __forceinline__ float ex2(float x) {
    float y; asm("ex2.approx.ftz.f32 %0, %1;" : "=f"(y) : "f"(x)); return y;
}
__device__ __forceinline__ double pk2(float lo, float hi) {
    double d; asm("mov.b64 %0, {%1, %2};" : "=d"(d) : "f"(lo), "f"(hi)); return d;
}
__device__ __forceinline__ void upk2(double d, float& lo, float& hi) {
    asm("mov.b64 {%0, %1}, %2;" : "=f"(lo), "=f"(hi) : "d"(d));
}
__device__ __forceinline__ double fma2(double a, double b, double c) {
    double d; asm("fma.rn.f32x2 %0, %1, %2, %3;" : "=d"(d) : "d"(a), "d"(b), "d"(c)); return d;
}
__device__ __forceinline__ double mul2(double a, double b) {
    double d; asm("mul.rn.f32x2 %0, %1, %2;" : "=d"(d) : "d"(a), "d"(b)); return d;
}
__device__ __forceinline__ double add2(double a, double b) {
    double d; asm("add.rn.f32x2 %0, %1, %2;" : "=d"(d) : "d"(a), "d"(b)); return d;
}
__device__ __forceinline__ void cp16(unsigned s, const void* g) {
    asm volatile("cp.async.cg.shared.global [%0], [%1], 16;" :: "r"(s), "l"(g));
}
__device__ __forceinline__ unsigned packh2(float hi, float lo) {
    unsigned r; asm("cvt.rn.f16x2.f32 %0, %1, %2;" : "=r"(r) : "f"(hi), "f"(lo)); return r;
}
__device__ __forceinline__ unsigned pack2h(__half a, __half b) {
    return (unsigned)__half_as_ushort(a) | ((unsigned)__half_as_ushort(b) << 16);
}
__device__ __forceinline__ void split16(float x, __half& hi, __half& lo) {
    hi = __float2half_rn(x);
    lo = __float2half_rn(x - __half2float(hi));
}
__device__ __forceinline__ void mma16816(float* d, const unsigned* a, const unsigned* b) {
    asm volatile(
        "mma.sync.aligned.m16n8k16.row.col.f32.f16.f16.f32 "
        "{%0,%1,%2,%3}, {%4,%5,%6,%7}, {%8,%9}, {%0,%1,%2,%3};"
        : "+f"(d[0]), "+f"(d[1]), "+f"(d[2]), "+f"(d[3])
        : "r"(a[0]), "r"(a[1]), "r"(a[2]), "r"(a[3]), "r"(b[0]), "r"(b[1]));
}

// ---------------------------------------------------------------------------
// Kernel 1: fused QKV projection (unchanged R10 core).
// ---------------------------------------------------------------------------
#define PXS 68
#define PXB (16 * PXS * 4)
#define PWB (3 * 64 * 16 * 4)
#define PSTAGE (PXB + PWB)

__global__ __launch_bounds__(128, 4)
void proj_kernel(const float* __restrict__ x,
                 const float* __restrict__ Wk,
                 const float* __restrict__ Wq,
                 const float* __restrict__ Wv) {
    __shared__ __align__(16) char sbuf[33280];

    const int tid = threadIdx.x;
    const int row = tid & 15;
    const int seg = tid >> 4;
    const long row0 = (long)blockIdx.x * 16;

    double aK[8], aQ[8], aV[8];
#pragma unroll
    for (int i = 0; i < 8; i++) { aK[i] = 0.0; aQ[i] = 0.0; aV[i] = 0.0; }

    const float4* xg = (const float4*)x;
    const float4* wg[3] = { (const float4*)Wk, (const float4*)Wq, (const float4*)Wv };

    auto load_chunk = [&](int buf, int cc) {
        unsigned sxa = (unsigned)__cvta_generic_to_shared(sbuf + buf * PSTAGE);
        unsigned swa = sxa + PXB;
        for (int i = tid; i < 256; i += 128) {
            int r = i >> 4, c4 = i & 15;
            cp16(sxa + (unsigned)(r * PXS + c4 * 4) * 4u,
                 xg + (row0 + r) * 96 + cc * 16 + c4);
        }
        for (int i = tid; i < 768; i += 128) {
            int m = i >> 8, j = i & 255;
            cp16(swa + (unsigned)(m * 256 + j) * 16u, wg[m] + cc * 256 + j);
        }
        asm volatile("cp.async.commit_group;");
    };

    load_chunk(0, 0);

    for (int cc = 0; cc < 6; cc++) {
        const int buf = cc & 1;
        if (cc < 5) {
            load_chunk(buf ^ 1, cc + 1);
            asm volatile("cp.async.wait_group 1;");
        } else {
            asm volatile("cp.async.wait_group 0;");
        }
        __syncthreads();

        const float* sx = (const float*)(sbuf + buf * PSTAGE);
        const float* sw = (const float*)(sbuf + buf * PSTAGE + PXB);

        float xv8[8];
        {
            const float4* xr4 = (const float4*)&sx[row * PXS + seg * 8];
            float4 a = xr4[0], c = xr4[1];
            xv8[0]=a.x; xv8[1]=a.y; xv8[2]=a.z; xv8[3]=a.w;
            xv8[4]=c.x; xv8[5]=c.y; xv8[6]=c.z; xv8[7]=c.w;
        }
        const int cbase = seg * 8;
#pragma unroll
        for (int c = 0; c < 8; c++) {
            double xv2 = pk2(xv8[c], xv8[c]);
            const double2* wk2 = (const double2*)&sw[0 * 1024 + (cbase + c) * 16];
            const double2* wq2 = (const double2*)&sw[1 * 1024 + (cbase + c) * 16];
            const double2* wv2 = (const double2*)&sw[2 * 1024 + (cbase + c) * 16];
#pragma unroll
            for (int m = 0; m < 4; m++) {
                double2 k = wk2[m], q = wq2[m], v = wv2[m];
                aK[2*m+0] = fma2(xv2, k.x, aK[2*m+0]);
                aK[2*m+1] = fma2(xv2, k.y, aK[2*m+1]);
                aQ[2*m+0] = fma2(xv2, q.x, aQ[2*m+0]);
                aQ[2*m+1] = fma2(xv2, q.y, aQ[2*m+1]);
                aV[2*m+0] = fma2(xv2, v.x, aV[2*m+0]);
                aV[2*m+1] = fma2(xv2, v.y, aV[2*m+1]);
            }
        }
        __syncthreads();
    }

    double* scomb = (double*)sbuf;   // [7][16][24]
    if (seg != 0) {
        double* d = &scomb[((seg - 1) * 16 + row) * 24];
#pragma unroll
        for (int i = 0; i < 8; i++) {
            d[i] = aK[i]; d[8 + i] = aQ[i]; d[16 + i] = aV[i];
        }
    }
    __syncthreads();
    if (seg == 0) {
        const float qscale = 0.25f * 1.4426950408889634f;  // H^-0.5 * log2(e)
        const double qs2 = pk2(qscale, qscale);
        float kf[16], qf[16], vf[16];
#pragma unroll
        for (int i = 0; i < 8; i++) {
            double k = aK[i], q = aQ[i], v = aV[i];
#pragma unroll
            for (int s = 0; s < 7; s++) {
                const double* d = &scomb[(s * 16 + row) * 24];
                k = add2(k, d[i]); q = add2(q, d[8 + i]); v = add2(v, d[16 + i]);
            }
            q = mul2(q, qs2);
            upk2(k, kf[2*i], kf[2*i+1]);
            upk2(q, qf[2*i], qf[2*i+1]);
            upk2(v, vf[2*i], vf[2*i+1]);
        }

        const long r = row0 + row;
        const int bb = (int)(r >> 12);
        const int tt = (int)(r & (T_ - 1));

        unsigned uqh[8], uql[8], ukh[8], ukl[8];
#pragma unroll
        for (int i = 0; i < 8; i++) {
            __half h0, l0, h1, l1;
            split16(qf[2*i], h0, l0); split16(qf[2*i+1], h1, l1);
            uqh[i] = pack2h(h0, h1); uql[i] = pack2h(l0, l1);
            split16(kf[2*i], h0, l0); split16(kf[2*i+1], h1, l1);
            ukh[i] = pack2h(h0, h1); ukl[i] = pack2h(l0, l1);
        }
        g_qh_[r*2+0] = make_uint4(uqh[0],uqh[1],uqh[2],uqh[3]);
        g_qh_[r*2+1] = make_uint4(uqh[4],uqh[5],uqh[6],uqh[7]);
        g_ql_[r*2+0] = make_uint4(uql[0],uql[1],uql[2],uql[3]);
        g_ql_[r*2+1] = make_uint4(uql[4],uql[5],uql[6],uql[7]);
        g_kh_[r*2+0] = make_uint4(ukh[0],ukh[1],ukh[2],ukh[3]);
        g_kh_[r*2+1] = make_uint4(ukh[4],ukh[5],ukh[6],ukh[7]);
        g_kl_[r*2+0] = make_uint4(ukl[0],ukl[1],ukl[2],ukl[3]);
        g_kl_[r*2+1] = make_uint4(ukl[4],ukl[5],ukl[6],ukl[7]);

        __half* vh = (__half*)g_vh_;
        __half* vl = (__half*)g_vl_;
#pragma unroll
        for (int i = 0; i < 16; i++) {
            __half h0, l0; split16(vf[i], h0, l0);
            vh[(size_t)(bb * 16 + i) * T_ + tt] = h0;
            vl[(size_t)(bb * 16 + i) * T_ + tt] = l0;
        }
    }
}

// ---------------------------------------------------------------------------
// Kernel 2: tensor-core causal flash attention (R10 core) + in-block
// reduction: the 4 warps' partials are tree-summed via smem, one global
// slot per (split, tile, b). Mainloop is per-warp (no block syncs).
// ---------------------------------------------------------------------------
__global__ __launch_bounds__(128, 4)
void attn_kernel() {
    // per warp: 2 bufs x 3072 = 6144 B; reduction overlay: 8704 B
    __shared__ __align__(16) char sbuf[4 * 6144];

    const int tid  = threadIdx.x;
    const int w    = tid >> 5;
    const int lane = tid & 31;
    const int g    = lane >> 2;
    const int tig  = lane & 3;
    const int b    = blockIdx.z;
    const int split = blockIdx.y;
    const int tile  = (int)gridDim.x - 1 - (int)blockIdx.x;  // heavy-first
    const int q_start = tile * 32;
    const int n_keys = q_start + 32;
    const int len = ((n_keys + 127) >> 7) << 4;
    const int kb  = split * len;
    const int ke  = min(kb + len, n_keys);

    unsigned qh[2][4], ql[2][4];
    {
        const char* qhb = (const char*)g_qh_;
        const char* qlb = (const char*)g_ql_;
        const size_t qrow0 = (size_t)b * T_ + q_start;
#pragma unroll
        for (int mt = 0; mt < 2; mt++)
#pragma unroll
            for (int p4 = 0; p4 < 4; p4++) {
                int roff = mt * 16 + g + ((p4 & 1) << 3);
                int hoff = tig * 2 + ((p4 >> 1) << 3);
                size_t off = (qrow0 + roff) * 32 + hoff * 2;
                qh[mt][p4] = *(const unsigned*)(qhb + off);
                ql[mt][p4] = *(const unsigned*)(qlb + off);
            }
    }

    float Do[2][2][4];
#pragma unroll
    for (int a = 0; a < 2; a++)
#pragma unroll
        for (int c = 0; c < 2; c++)
#pragma unroll
            for (int e = 0; e < 4; e++) Do[a][c][e] = 0.f;
    float l[2][2] = {{0.f, 0.f}, {0.f, 0.f}};

    char* wb = sbuf + w * 6144;
    const __half* khg = (const __half*)g_kh_ + (size_t)b * T_ * 16;
    const __half* klg = (const __half*)g_kl_ + (size_t)b * T_ * 16;
    const __half* vhg = (const __half*)g_vh_ + (size_t)b * 16 * T_;
    const __half* vlg = (const __half*)g_vl_ + (size_t)b * 16 * T_;

    auto load_chunk = [&](int bf, int t0) {
        unsigned sa = (unsigned)__cvta_generic_to_shared(wb + bf * 3072);
        const int e = lane >> 1;
        const int hf = lane & 1;
        cp16(sa +        (unsigned)(e * 48 + hf * 16), khg + (size_t)(t0 + e) * 16 + hf * 8);
        cp16(sa + 768u  + (unsigned)(e * 48 + hf * 16), klg + (size_t)(t0 + e) * 16 + hf * 8);
        cp16(sa + 1536u + (unsigned)(e * 48 + hf * 16), vhg + (size_t)e * T_ + t0 + hf * 8);
        cp16(sa + 2304u + (unsigned)(e * 48 + hf * 16), vlg + (size_t)e * T_ + t0 + hf * 8);
        asm volatile("cp.async.commit_group;");
    };

    auto compute = [&](int bf, int t0, bool masked) {
        const char* kh_s = wb + bf * 3072;
        const char* kl_s = kh_s + 768;
        const char* vh_s = kh_s + 1536;
        const char* vl_s = kh_s + 2304;

        unsigned khb[2][2], klb[2][2], vhb[2][2], vlb[2][2];
#pragma unroll
        for (int nt = 0; nt < 2; nt++) {
            int key = g + nt * 8;
            khb[nt][0] = *(const unsigned*)(kh_s + key * 48 + tig * 4);
            khb[nt][1] = *(const unsigned*)(kh_s + key * 48 + 16 + tig * 4);
            klb[nt][0] = *(const unsigned*)(kl_s + key * 48 + tig * 4);
            klb[nt][1] = *(const unsigned*)(kl_s + key * 48 + 16 + tig * 4);
            int h = g + nt * 8;
            vhb[nt][0] = *(const unsigned*)(vh_s + h * 48 + tig * 4);
            vhb[nt][1] = *(const unsigned*)(vh_s + h * 48 + 16 + tig * 4);
            vlb[nt][0] = *(const unsigned*)(vl_s + h * 48 + tig * 4);
            vlb[nt][1] = *(const unsigned*)(vl_s + h * 48 + 16 + tig * 4);
        }

#pragma unroll
        for (int mt = 0; mt < 2; mt++) {
            float ds[2][4];
#pragma unroll
            for (int nt = 0; nt < 2; nt++) {
#pragma unroll
                for (int e = 0; e < 4; e++) ds[nt][e] = 0.f;
                mma16816(ds[nt], qh[mt], khb[nt]);
                mma16816(ds[nt], qh[mt], klb[nt]);
                mma16816(ds[nt], ql[mt], khb[nt]);
            }
            const int rowq0 = q_start + mt * 16 + g;
#pragma unroll
            for (int nt = 0; nt < 2; nt++) {
                const int kc = t0 + nt * 8 + 2 * tig;
#pragma unroll
                for (int e = 0; e < 4; e++) {
                    float p = ex2(ds[nt][e]);
                    if (masked) {
                        int key = kc + (e & 1);
                        int rq  = rowq0 + ((e >> 1) << 3);
                        p = (key <= rq) ? p : 0.f;
                    }
                    ds[nt][e] = p;
                    l[mt][e >> 1] += p;
                }
            }
            unsigned pa[4];
            pa[0] = packh2(ds[0][1], ds[0][0]);
            pa[1] = packh2(ds[0][3], ds[0][2]);
            pa[2] = packh2(ds[1][1], ds[1][0]);
            pa[3] = packh2(ds[1][3], ds[1][2]);
#pragma unroll
            for (int nh = 0; nh < 2; nh++) {
                mma16816(Do[mt][nh], pa, vhb[nh]);
                mma16816(Do[mt][nh], pa, vlb[nh]);
            }
        }
    };

    int t0 = kb + w * 16;
    if (t0 < ke) {
        load_chunk(0, t0);
        int bf = 0;
        while (t0 < ke) {
            int tn = t0 + 64;
            if (tn < ke) {
                load_chunk(bf ^ 1, tn);
                asm volatile("cp.async.wait_group 1;");
            } else {
                asm volatile("cp.async.wait_group 0;");
            }
            __syncwarp();
            compute(bf, t0, t0 >= q_start);
            __syncwarp();
            bf ^= 1; t0 = tn;
        }
    }

    // reduce row sums over the quad (cols live in tig)
#pragma unroll
    for (int off = 1; off <= 2; off <<= 1)
#pragma unroll
        for (int mt = 0; mt < 2; mt++) {
            l[mt][0] += __shfl_xor_sync(0xffffffffu, l[mt][0], off);
            l[mt][1] += __shfl_xor_sync(0xffffffffu, l[mt][1], off);
        }

    // ---- in-block reduction across the 4 warps ----
    __syncthreads();                       // all warps done with sbuf pipelines
    float* sred = (float*)sbuf;            // [4][32][16]
    float* sl   = (float*)(sbuf + 8192);   // [4][32]
#pragma unroll
    for (int mt = 0; mt < 2; mt++) {
#pragma unroll
        for (int nt = 0; nt < 2; nt++)
#pragma unroll
            for (int e = 0; e < 4; e++) {
                int rl = mt * 16 + g + ((e >> 1) << 3);
                int cl = nt * 8 + tig * 2 + (e & 1);
                sred[(w * 32 + rl) * 16 + cl] = Do[mt][nt][e];
            }
        if (tig == 0) {
            sl[w * 32 + mt * 16 + g]     = l[mt][0];
            sl[w * 32 + mt * 16 + g + 8] = l[mt][1];
        }
    }
    __syncthreads();

    {
        const int row = tid >> 2;          // 0..31
        const int cg  = tid & 3;           // float4 column group
        float4 a = make_float4(0.f, 0.f, 0.f, 0.f);
#pragma unroll
        for (int ww = 0; ww < 4; ww++) {
            float4 t = *(const float4*)&sred[(ww * 32 + row) * 16 + cg * 4];
            a.x += t.x; a.y += t.y; a.z += t.z; a.w += t.w;
        }
        const size_t prow = (size_t)split * BT_ + (size_t)b * T_ + q_start + row;
        ((float4*)(g_pacc + prow * 16))[cg] = a;
        if (cg == 0) {
            float ls = sl[row] + sl[32 + row] + sl[64 + row] + sl[96 + row];
            g_pl[prow] = ls;
        }
    }
}

// ---------------------------------------------------------------------------
// Kernel 3: combine 8 split slots. 4 threads per output row.
// ---------------------------------------------------------------------------
__global__ __launch_bounds__(256)
void combine_kernel(float* __restrict__ out) {
    const int idx = blockIdx.x * 256 + threadIdx.x;   // 0 .. BT_*4-1
    const int row = idx >> 2;
    const int cg  = idx & 3;

    float l = 0.f;
#pragma unroll
    for (int s = 0; s < SPLITS; s++) l += g_pl[(size_t)s * BT_ + row];
    const float inv = 1.0f / l;

    float4 a = make_float4(0.f, 0.f, 0.f, 0.f);
#pragma unroll
    for (int s = 0; s < SPLITS; s++) {
        float4 t = ((const float4*)(g_pacc + ((size_t)s * BT_ + row) * 16))[cg];
        a.x += t.x; a.y += t.y; a.z += t.z; a.w += t.w;
    }
    ((float4*)(out + (size_t)row * 16))[cg] =
        make_float4(a.x * inv, a.y * inv, a.z * inv, a.w * inv);
}

extern "C" void kernel_launch(void* const* d_in, const int* in_sizes, int n_in,
                              void* d_out, int out_size) {
    const float* x  = (const float*)d_in[0];
    const float* Wk = (const float*)d_in[1];
    const float* Wq = (const float*)d_in[2];
    const float* Wv = (const float*)d_in[3];
    float* out = (float*)d_out;

    proj_kernel<<<BT_ / 16, 128>>>(x, Wk, Wq, Wv);
    attn_kernel<<<dim3(T_ / 32, SPLITS, B_), 128>>>();
    combine_kernel<<<BT_ * 4 / 256, 256>>>(out);
}

// round 12
// speedup vs baseline: 2.4860x; 1.2365x over previous
#include <cuda_runtime.h>
#include <cuda_fp16.h>
#include <cstdint>

// Problem: B=4, T=4096, C=384 (n_embd), H=16 (head_size)
// out[b,t,:] = softmax_causal( (x@Wq)(x@Wk)^T / sqrt(H) ) @ (x@Wv)

#define B_     4
#define T_     4096
#define C_     384
#define H_     16
#define BT_    (B_ * T_)
#define SPLITS 8

// fp16 hi/lo planes. q pre-scaled by H^-0.5 * log2(e). q,k: [token][16h].
// v: [b][h][t] (transposed). Attention-kernel layouts (unchanged from R11).
__device__ uint4 g_qh_[BT_ * 2];
__device__ uint4 g_ql_[BT_ * 2];
__device__ uint4 g_kh_[BT_ * 2];
__device__ uint4 g_kl_[BT_ * 2];
__device__ uint4 g_vh_[B_ * 16 * T_ / 8];
__device__ uint4 g_vl_[B_ * 16 * T_ / 8];
__device__ float g_pacc[(size_t)SPLITS * BT_ * H_];
__device__ float g_pl[SPLITS * BT_];
// W fragments: [kk=24][nt=6][r=2][plane=2][lane=32] fp16x2 (36 KB)
__device__ unsigned g_wfrag[24 * 6 * 2 * 2 * 32];

// ---------------- helpers ----------------
__device__ __forceinline__ float ex2(float x) {
    float y; asm("ex2.approx.ftz.f32 %0, %1;" : "=f"(y) : "f"(x)); return y;
}
__device__ __forceinline__ void cp16(unsigned s, const void* g) {
    asm volatile("cp.async.cg.shared.global [%0], [%1], 16;" :: "r"(s), "l"(g));
}
__device__ __forceinline__ unsigned packh2(float hi, float lo) {
    unsigned r; asm("cvt.rn.f16x2.f32 %0, %1, %2;" : "=r"(r) : "f"(hi), "f"(lo)); return r;
}
__device__ __forceinline__ unsigned pack2h(__half a, __half b) {  // a = lower
    return (unsigned)__half_as_ushort(a) | ((unsigned)__half_as_ushort(b) << 16);
}
__device__ __forceinline__ void split16(float x, __half& hi, __half& lo) {
    hi = __float2half_rn(x);
    lo = __float2half_rn(x - __half2float(hi));
}
__device__ __forceinline__ void mma16816(float* d, const unsigned* a, const unsigned* b) {
    asm volatile(
        "mma.sync.aligned.m16n8k16.row.col.f32.f16.f16.f32 "
        "{%0,%1,%2,%3}, {%4,%5,%6,%7}, {%8,%9}, {%0,%1,%2,%3};"
        : "+f"(d[0]), "+f"(d[1]), "+f"(d[2]), "+f"(d[3])
        : "r"(a[0]), "r"(a[1]), "r"(a[2]), "r"(a[3]), "r"(b[0]), "r"(b[1]));
}

// ---------------------------------------------------------------------------
// Kernel 0: W prep — build fragment-exact hi/lo fp16 W tiles.
// Output n: 0..15 = K, 16..31 = Q (pre-scaled), 32..47 = V.
// idx = (((kk*6+nt)*2+r)*2+pl)*32+lane ; entry = pack(W[k_even][n], W[k_odd][n])
// ---------------------------------------------------------------------------
__global__ __launch_bounds__(256)
void prep_kernel(const float* __restrict__ Wk,
                 const float* __restrict__ Wq,
                 const float* __restrict__ Wv) {
    const int idx = blockIdx.x * 256 + threadIdx.x;   // 0..36863
    const int lane = idx & 31;
    const int pl = (idx >> 5) & 1;
    const int r  = (idx >> 6) & 1;
    const int rem = idx >> 7;
    const int nt = rem % 6;
    const int kk = rem / 6;
    const int gg = lane >> 2, tg = lane & 3;
    const int n  = nt * 8 + gg;
    const int k0 = kk * 16 + 2 * tg + r * 8;

    const float* Ws = (n < 16) ? Wk : ((n < 32) ? Wq : Wv);
    const int h = n & 15;
    const float s = (n >= 16 && n < 32) ? (0.25f * 1.4426950408889634f) : 1.0f;
    float v0 = Ws[k0 * 16 + h] * s;
    float v1 = Ws[(k0 + 1) * 16 + h] * s;
    __half h0, l0, h1, l1;
    split16(v0, h0, l0); split16(v1, h1, l1);
    g_wfrag[idx] = pl ? pack2h(l0, l1) : pack2h(h0, h1);
}

// ---------------------------------------------------------------------------
// Kernel 1: tensor-core QKV projection. 256 blocks x 128 threads (4 warps).
// Warp = 16 rows x 48 outputs x K=384 (24 k-steps, 18 MMAs each).
// A (x) loaded from global as float2 with depth-2 prefetch, split hi/lo in
// registers. B (W) from g_wfrag: one coalesced L1-resident LDG per fragment.
// No shared memory. Epilogue writes attention-layout fp16 hi/lo planes.
// ---------------------------------------------------------------------------
__global__ __launch_bounds__(128, 4)
void proj_mma(const float* __restrict__ x) {
    const int tid  = threadIdx.x;
    const int w    = tid >> 5;
    const int lane = tid & 31;
    const int g    = lane >> 2, tig = lane & 3;
    const int row0 = blockIdx.x * 64 + w * 16;
    const int ra = row0 + g, rb = ra + 8;

    const float* pa = x + (size_t)ra * C_ + 2 * tig;
    const float* pb = x + (size_t)rb * C_ + 2 * tig;

    float D[6][4];
#pragma unroll
    for (int nt = 0; nt < 6; nt++)
#pragma unroll
        for (int e = 0; e < 4; e++) D[nt][e] = 0.f;

    auto loadA = [&](float2* d, int kk) {
        d[0] = *(const float2*)(pa + kk * 16);
        d[1] = *(const float2*)(pb + kk * 16);
        d[2] = *(const float2*)(pa + kk * 16 + 8);
        d[3] = *(const float2*)(pb + kk * 16 + 8);
    };

    float2 c0[4], c1[4];
    loadA(c0, 0);
    loadA(c1, 1);

#pragma unroll 2
    for (int kk = 0; kk < 24; kk++) {
        float2 c2[4];
        if (kk + 2 < 24) loadA(c2, kk + 2);

        unsigned ah[4], al[4];
#pragma unroll
        for (int p = 0; p < 4; p++) {
            __half h0, l0, h1, l1;
            split16(c0[p].x, h0, l0);
            split16(c0[p].y, h1, l1);
            ah[p] = pack2h(h0, h1);
            al[p] = pack2h(l0, l1);
        }

        const unsigned* wkb = g_wfrag + kk * 768 + lane;
#pragma unroll
        for (int nt = 0; nt < 6; nt++) {
            const unsigned* wn = wkb + nt * 128;
            unsigned bh[2], bl[2];
            bh[0] = wn[0];   bl[0] = wn[32];
            bh[1] = wn[64];  bl[1] = wn[96];
            mma16816(D[nt], ah, bh);
            mma16816(D[nt], al, bh);
            mma16816(D[nt], ah, bl);
        }
#pragma unroll
        for (int p = 0; p < 4; p++) { c0[p] = c1[p]; c1[p] = c2[p]; }
    }

    // ---- epilogue: split16 + write attention layouts ----
    const int bb = ra >> 12;                 // batch (block never straddles)
    unsigned* kh = (unsigned*)g_kh_;
    unsigned* kl = (unsigned*)g_kl_;
    unsigned* qh = (unsigned*)g_qh_;
    unsigned* ql = (unsigned*)g_ql_;
    __half* vh = (__half*)g_vh_;
    __half* vl = (__half*)g_vl_;

#pragma unroll
    for (int rr = 0; rr < 2; rr++) {
        const int token = rr ? rb : ra;
        const int e0 = rr * 2;               // D elems for this row: e0, e0+1
        __half h0, l0, h1, l1;

        // K: nt 0 -> h 2tig..2tig+1 ; nt 1 -> +8
        split16(D[0][e0], h0, l0); split16(D[0][e0+1], h1, l1);
        kh[token * 8 + tig]     = pack2h(h0, h1);
        kl[token * 8 + tig]     = pack2h(l0, l1);
        split16(D[1][e0], h0, l0); split16(D[1][e0+1], h1, l1);
        kh[token * 8 + tig + 4] = pack2h(h0, h1);
        kl[token * 8 + tig + 4] = pack2h(l0, l1);

        // Q: nt 2,3 (already scaled via W prep)
        split16(D[2][e0], h0, l0); split16(D[2][e0+1], h1, l1);
        qh[token * 8 + tig]     = pack2h(h0, h1);
        ql[token * 8 + tig]     = pack2h(l0, l1);
        split16(D[3][e0], h0, l0); split16(D[3][e0+1], h1, l1);
        qh[token * 8 + tig + 4] = pack2h(h0, h1);
        ql[token * 8 + tig + 4] = pack2h(l0, l1);

        // V: nt 4,5 -> transposed [b][h][t]
        const int t = token & (T_ - 1);
#pragma unroll
        for (int nv = 0; nv < 2; nv++) {
            const int hb = bb * 16 + nv * 8 + 2 * tig;
            split16(D[4 + nv][e0],   h0, l0);
            split16(D[4 + nv][e0+1], h1, l1);
            vh[(size_t)hb * T_ + t]       = h0;
            vl[(size_t)hb * T_ + t]       = l0;
            vh[(size_t)(hb + 1) * T_ + t] = h1;
            vl[(size_t)(hb + 1) * T_ + t] = l1;
        }
    }
}

// ---------------------------------------------------------------------------
// Kernel 2: tensor-core causal flash attention (unchanged R11).
// ---------------------------------------------------------------------------
__global__ __launch_bounds__(128, 4)
void attn_kernel() {
    __shared__ __align__(16) char sbuf[4 * 6144];

    const int tid  = threadIdx.x;
    const int w    = tid >> 5;
    const int lane = tid & 31;
    const int g    = lane >> 2;
    const int tig  = lane & 3;
    const int b    = blockIdx.z;
    const int split = blockIdx.y;
    const int tile  = (int)gridDim.x - 1 - (int)blockIdx.x;  // heavy-first
    const int q_start = tile * 32;
    const int n_keys = q_start + 32;
    const int len = ((n_keys + 127) >> 7) << 4;
    const int kb  = split * len;
    const int ke  = min(kb + len, n_keys);

    unsigned qh[2][4], ql[2][4];
    {
        const char* qhb = (const char*)g_qh_;
        const char* qlb = (const char*)g_ql_;
        const size_t qrow0 = (size_t)b * T_ + q_start;
#pragma unroll
        for (int mt = 0; mt < 2; mt++)
#pragma unroll
            for (int p4 = 0; p4 < 4; p4++) {
                int roff = mt * 16 + g + ((p4 & 1) << 3);
                int hoff = tig * 2 + ((p4 >> 1) << 3);
                size_t off = (qrow0 + roff) * 32 + hoff * 2;
                qh[mt][p4] = *(const unsigned*)(qhb + off);
                ql[mt][p4] = *(const unsigned*)(qlb + off);
            }
    }

    float Do[2][2][4];
#pragma unroll
    for (int a = 0; a < 2; a++)
#pragma unroll
        for (int c = 0; c < 2; c++)
#pragma unroll
            for (int e = 0; e < 4; e++) Do[a][c][e] = 0.f;
    float l[2][2] = {{0.f, 0.f}, {0.f, 0.f}};

    char* wb = sbuf + w * 6144;
    const __half* khg = (const __half*)g_kh_ + (size_t)b * T_ * 16;
    const __half* klg = (const __half*)g_kl_ + (size_t)b * T_ * 16;
    const __half* vhg = (const __half*)g_vh_ + (size_t)b * 16 * T_;
    const __half* vlg = (const __half*)g_vl_ + (size_t)b * 16 * T_;

    auto load_chunk = [&](int bf, int t0) {
        unsigned sa = (unsigned)__cvta_generic_to_shared(wb + bf * 3072);
        const int e = lane >> 1;
        const int hf = lane & 1;
        cp16(sa +        (unsigned)(e * 48 + hf * 16), khg + (size_t)(t0 + e) * 16 + hf * 8);
        cp16(sa + 768u  + (unsigned)(e * 48 + hf * 16), klg + (size_t)(t0 + e) * 16 + hf * 8);
        cp16(sa + 1536u + (unsigned)(e * 48 + hf * 16), vhg + (size_t)e * T_ + t0 + hf * 8);
        cp16(sa + 2304u + (unsigned)(e * 48 + hf * 16), vlg + (size_t)e * T_ + t0 + hf * 8);
        asm volatile("cp.async.commit_group;");
    };

    auto compute = [&](int bf, int t0, bool masked) {
        const char* kh_s = wb + bf * 3072;
        const char* kl_s = kh_s + 768;
        const char* vh_s = kh_s + 1536;
        const char* vl_s = kh_s + 2304;

        unsigned khb[2][2], klb[2][2], vhb[2][2], vlb[2][2];
#pragma unroll
        for (int nt = 0; nt < 2; nt++) {
            int key = g + nt * 8;
            khb[nt][0] = *(const unsigned*)(kh_s + key * 48 + tig * 4);
            khb[nt][1] = *(const unsigned*)(kh_s + key * 48 + 16 + tig * 4);
            klb[nt][0] = *(const unsigned*)(kl_s + key * 48 + tig * 4);
            klb[nt][1] = *(const unsigned*)(kl_s + key * 48 + 16 + tig * 4);
            int h = g + nt * 8;
            vhb[nt][0] = *(const unsigned*)(vh_s + h * 48 + tig * 4);
            vhb[nt][1] = *(const unsigned*)(vh_s + h * 48 + 16 + tig * 4);
            vlb[nt][0] = *(const unsigned*)(vl_s + h * 48 + tig * 4);
            vlb[nt][1] = *(const unsigned*)(vl_s + h * 48 + 16 + tig * 4);
        }

#pragma unroll
        for (int mt = 0; mt < 2; mt++) {
            float ds[2][4];
#pragma unroll
            for (int nt = 0; nt < 2; nt++) {
#pragma unroll
                for (int e = 0; e < 4; e++) ds[nt][e] = 0.f;
                mma16816(ds[nt], qh[mt], khb[nt]);
                mma16816(ds[nt], qh[mt], klb[nt]);
                mma16816(ds[nt], ql[mt], khb[nt]);
            }
            const int rowq0 = q_start + mt * 16 + g;
#pragma unroll
            for (int nt = 0; nt < 2; nt++) {
                const int kc = t0 + nt * 8 + 2 * tig;
#pragma unroll
                for (int e = 0; e < 4; e++) {
                    float p = ex2(ds[nt][e]);
                    if (masked) {
                        int key = kc + (e & 1);
                        int rq  = rowq0 + ((e >> 1) << 3);
                        p = (key <= rq) ? p : 0.f;
                    }
                    ds[nt][e] = p;
                    l[mt][e >> 1] += p;
                }
            }
            unsigned pa[4];
            pa[0] = packh2(ds[0][1], ds[0][0]);
            pa[1] = packh2(ds[0][3], ds[0][2]);
            pa[2] = packh2(ds[1][1], ds[1][0]);
            pa[3] = packh2(ds[1][3], ds[1][2]);
#pragma unroll
            for (int nh = 0; nh < 2; nh++) {
                mma16816(Do[mt][nh], pa, vhb[nh]);
                mma16816(Do[mt][nh], pa, vlb[nh]);
            }
        }
    };

    int t0 = kb + w * 16;
    if (t0 < ke) {
        load_chunk(0, t0);
        int bf = 0;
        while (t0 < ke) {
            int tn = t0 + 64;
            if (tn < ke) {
                load_chunk(bf ^ 1, tn);
                asm volatile("cp.async.wait_group 1;");
            } else {
                asm volatile("cp.async.wait_group 0;");
            }
            __syncwarp();
            compute(bf, t0, t0 >= q_start);
            __syncwarp();
            bf ^= 1; t0 = tn;
        }
    }

#pragma unroll
    for (int off = 1; off <= 2; off <<= 1)
#pragma unroll
        for (int mt = 0; mt < 2; mt++) {
            l[mt][0] += __shfl_xor_sync(0xffffffffu, l[mt][0], off);
            l[mt][1] += __shfl_xor_sync(0xffffffffu, l[mt][1], off);
        }

    __syncthreads();
    float* sred = (float*)sbuf;            // [4][32][16]
    float* sl   = (float*)(sbuf + 8192);   // [4][32]
#pragma unroll
    for (int mt = 0; mt < 2; mt++) {
#pragma unroll
        for (int nt = 0; nt < 2; nt++)
#pragma unroll
            for (int e = 0; e < 4; e++) {
                int rl = mt * 16 + g + ((e >> 1) << 3);
                int cl = nt * 8 + tig * 2 + (e & 1);
                sred[(w * 32 + rl) * 16 + cl] = Do[mt][nt][e];
            }
        if (tig == 0) {
            sl[w * 32 + mt * 16 + g]     = l[mt][0];
            sl[w * 32 + mt * 16 + g + 8] = l[mt][1];
        }
    }
    __syncthreads();

    {
        const int row = tid >> 2;
        const int cg  = tid & 3;
        float4 a = make_float4(0.f, 0.f, 0.f, 0.f);
#pragma unroll
        for (int ww = 0; ww < 4; ww++) {
            float4 t = *(const float4*)&sred[(ww * 32 + row) * 16 + cg * 4];
            a.x += t.x; a.y += t.y; a.z += t.z; a.w += t.w;
        }
        const size_t prow = (size_t)split * BT_ + (size_t)b * T_ + q_start + row;
        ((float4*)(g_pacc + prow * 16))[cg] = a;
        if (cg == 0) {
            float ls = sl[row] + sl[32 + row] + sl[64 + row] + sl[96 + row];
            g_pl[prow] = ls;
        }
    }
}

// ---------------------------------------------------------------------------
// Kernel 3: combine 8 split slots. 4 threads per output row.
// ---------------------------------------------------------------------------
__global__ __launch_bounds__(256)
void combine_kernel(float* __restrict__ out) {
    const int idx = blockIdx.x * 256 + threadIdx.x;
    const int row = idx >> 2;
    const int cg  = idx & 3;

    float l = 0.f;
#pragma unroll
    for (int s = 0; s < SPLITS; s++) l += g_pl[(size_t)s * BT_ + row];
    const float inv = 1.0f / l;

    float4 a = make_float4(0.f, 0.f, 0.f, 0.f);
#pragma unroll
    for (int s = 0; s < SPLITS; s++) {
        float4 t = ((const float4*)(g_pacc + ((size_t)s * BT_ + row) * 16))[cg];
        a.x += t.x; a.y += t.y; a.z += t.z; a.w += t.w;
    }
    ((float4*)(out + (size_t)row * 16))[cg] =
        make_float4(a.x * inv, a.y * inv, a.z * inv, a.w * inv);
}

extern "C" void kernel_launch(void* const* d_in, const int* in_sizes, int n_in,
                              void* d_out, int out_size) {
    const float* x  = (const float*)d_in[0];
    const float* Wk = (const float*)d_in[1];
    const float* Wq = (const float*)d_in[2];
    const float* Wv = (const float*)d_in[3];
    float* out = (float*)d_out;

    prep_kernel<<<144, 256>>>(Wk, Wq, Wv);
    proj_mma<<<BT_ / 64, 128>>>(x);
    attn_kernel<<<dim3(T_ / 32, SPLITS, B_), 128>>>();
    combine_kernel<<<BT_ * 4 / 256, 256>>>(out);
}

// round 13
// speedup vs baseline: 2.5190x; 1.0133x over previous
#include <cuda_runtime.h>
#include <cuda_fp16.h>
#include <cstdint>

// Problem: B=4, T=4096, C=384 (n_embd), H=16 (head_size)
// out[b,t,:] = softmax_causal( (x@Wq)(x@Wk)^T / sqrt(H) ) @ (x@Wv)

#define B_     4
#define T_     4096
#define C_     384
#define H_     16
#define BT_    (B_ * T_)
#define SPLITS 4

// fp16 hi/lo planes. q pre-scaled by H^-0.5 * log2(e). q,k: [token][16h].
// v: [b][h][t] (transposed).
__device__ uint4 g_qh_[BT_ * 2];
__device__ uint4 g_ql_[BT_ * 2];
__device__ uint4 g_kh_[BT_ * 2];
__device__ uint4 g_kl_[BT_ * 2];
__device__ uint4 g_vh_[B_ * 16 * T_ / 8];
__device__ uint4 g_vl_[B_ * 16 * T_ / 8];
__device__ float g_pacc[(size_t)SPLITS * BT_ * H_];
__device__ float g_pl[SPLITS * BT_];
// W fragments: [kk=24][nt=6][r=2][plane=2][lane=32] fp16x2 (36 KB)
__device__ unsigned g_wfrag[24 * 6 * 2 * 2 * 32];

// ---------------- helpers ----------------
__device__ __forceinline__ float ex2(float x) {
    float y; asm("ex2.approx.ftz.f32 %0, %1;" : "=f"(y) : "f"(x)); return y;
}
__device__ __forceinline__ void cp16(unsigned s, const void* g) {
    asm volatile("cp.async.cg.shared.global [%0], [%1], 16;" :: "r"(s), "l"(g));
}
__device__ __forceinline__ unsigned packh2(float hi, float lo) {
    unsigned r; asm("cvt.rn.f16x2.f32 %0, %1, %2;" : "=r"(r) : "f"(hi), "f"(lo)); return r;
}
__device__ __forceinline__ unsigned pack2h(__half a, __half b) {  // a = lower
    return (unsigned)__half_as_ushort(a) | ((unsigned)__half_as_ushort(b) << 16);
}
__device__ __forceinline__ void split16(float x, __half& hi, __half& lo) {
    hi = __float2half_rn(x);
    lo = __float2half_rn(x - __half2float(hi));
}
__device__ __forceinline__ void mma16816(float* d, const unsigned* a, const unsigned* b) {
    asm volatile(
        "mma.sync.aligned.m16n8k16.row.col.f32.f16.f16.f32 "
        "{%0,%1,%2,%3}, {%4,%5,%6,%7}, {%8,%9}, {%0,%1,%2,%3};"
        : "+f"(d[0]), "+f"(d[1]), "+f"(d[2]), "+f"(d[3])
        : "r"(a[0]), "r"(a[1]), "r"(a[2]), "r"(a[3]), "r"(b[0]), "r"(b[1]));
}

// ---------------------------------------------------------------------------
// Kernel 0: W prep — fragment-exact hi/lo fp16 W tiles (unchanged R12).
// ---------------------------------------------------------------------------
__global__ __launch_bounds__(256)
void prep_kernel(const float* __restrict__ Wk,
                 const float* __restrict__ Wq,
                 const float* __restrict__ Wv) {
    const int idx = blockIdx.x * 256 + threadIdx.x;
    const int lane = idx & 31;
    const int pl = (idx >> 5) & 1;
    const int r  = (idx >> 6) & 1;
    const int rem = idx >> 7;
    const int nt = rem % 6;
    const int kk = rem / 6;
    const int gg = lane >> 2, tg = lane & 3;
    const int n  = nt * 8 + gg;
    const int k0 = kk * 16 + 2 * tg + r * 8;

    const float* Ws = (n < 16) ? Wk : ((n < 32) ? Wq : Wv);
    const int h = n & 15;
    const float s = (n >= 16 && n < 32) ? (0.25f * 1.4426950408889634f) : 1.0f;
    float v0 = Ws[k0 * 16 + h] * s;
    float v1 = Ws[(k0 + 1) * 16 + h] * s;
    __half h0, l0, h1, l1;
    split16(v0, h0, l0); split16(v1, h1, l1);
    g_wfrag[idx] = pl ? pack2h(l0, l1) : pack2h(h0, h1);
}

// ---------------------------------------------------------------------------
// Kernel 1: tensor-core QKV projection (R12 core, depth-3 A prefetch).
// ---------------------------------------------------------------------------
__global__ __launch_bounds__(128, 4)
void proj_mma(const float* __restrict__ x) {
    const int tid  = threadIdx.x;
    const int w    = tid >> 5;
    const int lane = tid & 31;
    const int g    = lane >> 2, tig = lane & 3;
    const int row0 = blockIdx.x * 64 + w * 16;
    const int ra = row0 + g, rb = ra + 8;

    const float* pa = x + (size_t)ra * C_ + 2 * tig;
    const float* pb = x + (size_t)rb * C_ + 2 * tig;

    float D[6][4];
#pragma unroll
    for (int nt = 0; nt < 6; nt++)
#pragma unroll
        for (int e = 0; e < 4; e++) D[nt][e] = 0.f;

    auto loadA = [&](float2* d, int kk) {
        d[0] = *(const float2*)(pa + kk * 16);
        d[1] = *(const float2*)(pb + kk * 16);
        d[2] = *(const float2*)(pa + kk * 16 + 8);
        d[3] = *(const float2*)(pb + kk * 16 + 8);
    };

    float2 c0[4], c1[4], c2[4];
    loadA(c0, 0);
    loadA(c1, 1);
    loadA(c2, 2);

#pragma unroll 3
    for (int kk = 0; kk < 24; kk++) {
        float2 c3[4];
        if (kk + 3 < 24) loadA(c3, kk + 3);

        unsigned ah[4], al[4];
#pragma unroll
        for (int p = 0; p < 4; p++) {
            __half h0, l0, h1, l1;
            split16(c0[p].x, h0, l0);
            split16(c0[p].y, h1, l1);
            ah[p] = pack2h(h0, h1);
            al[p] = pack2h(l0, l1);
        }

        const unsigned* wkb = g_wfrag + kk * 768 + lane;
#pragma unroll
        for (int nt = 0; nt < 6; nt++) {
            const unsigned* wn = wkb + nt * 128;
            unsigned bh[2], bl[2];
            bh[0] = wn[0];   bl[0] = wn[32];
            bh[1] = wn[64];  bl[1] = wn[96];
            mma16816(D[nt], ah, bh);
            mma16816(D[nt], al, bh);
            mma16816(D[nt], ah, bl);
        }
#pragma unroll
        for (int p = 0; p < 4; p++) { c0[p] = c1[p]; c1[p] = c2[p]; c2[p] = c3[p]; }
    }

    // ---- epilogue: split16 + attention layouts ----
    const int bb = ra >> 12;
    unsigned* kh = (unsigned*)g_kh_;
    unsigned* kl = (unsigned*)g_kl_;
    unsigned* qh = (unsigned*)g_qh_;
    unsigned* ql = (unsigned*)g_ql_;
    __half* vh = (__half*)g_vh_;
    __half* vl = (__half*)g_vl_;

#pragma unroll
    for (int rr = 0; rr < 2; rr++) {
        const int token = rr ? rb : ra;
        const int e0 = rr * 2;
        __half h0, l0, h1, l1;

        split16(D[0][e0], h0, l0); split16(D[0][e0+1], h1, l1);
        kh[token * 8 + tig]     = pack2h(h0, h1);
        kl[token * 8 + tig]     = pack2h(l0, l1);
        split16(D[1][e0], h0, l0); split16(D[1][e0+1], h1, l1);
        kh[token * 8 + tig + 4] = pack2h(h0, h1);
        kl[token * 8 + tig + 4] = pack2h(l0, l1);

        split16(D[2][e0], h0, l0); split16(D[2][e0+1], h1, l1);
        qh[token * 8 + tig]     = pack2h(h0, h1);
        ql[token * 8 + tig]     = pack2h(l0, l1);
        split16(D[3][e0], h0, l0); split16(D[3][e0+1], h1, l1);
        qh[token * 8 + tig + 4] = pack2h(h0, h1);
        ql[token * 8 + tig + 4] = pack2h(l0, l1);

        const int t = token & (T_ - 1);
#pragma unroll
        for (int nv = 0; nv < 2; nv++) {
            const int hb = bb * 16 + nv * 8 + 2 * tig;
            split16(D[4 + nv][e0],   h0, l0);
            split16(D[4 + nv][e0+1], h1, l1);
            vh[(size_t)hb * T_ + t]       = h0;
            vl[(size_t)hb * T_ + t]       = l0;
            vh[(size_t)(hb + 1) * T_ + t] = h1;
            vl[(size_t)(hb + 1) * T_ + t] = l1;
        }
    }
}

// ---------------------------------------------------------------------------
// Kernel 2: tensor-core causal flash attention. SPLITS=4; per-warp 3-stage
// cp.async pipeline (2 chunks in flight). In-block reduction unchanged.
// ---------------------------------------------------------------------------
__global__ __launch_bounds__(128, 4)
void attn_kernel() {
    // per warp: 3 bufs x 3072 = 9216 B -> 36864 B total
    __shared__ __align__(16) char sbuf[4 * 9216];

    const int tid  = threadIdx.x;
    const int w    = tid >> 5;
    const int lane = tid & 31;
    const int g    = lane >> 2;
    const int tig  = lane & 3;
    const int b    = blockIdx.z;
    const int split = blockIdx.y;
    const int tile  = (int)gridDim.x - 1 - (int)blockIdx.x;  // heavy-first
    const int q_start = tile * 32;
    const int n_keys = q_start + 32;
    const int len = ((n_keys + 16 * SPLITS - 1) / (16 * SPLITS)) * 16;
    const int kb  = split * len;
    const int ke  = min(kb + len, n_keys);

    unsigned qh[2][4], ql[2][4];
    {
        const char* qhb = (const char*)g_qh_;
        const char* qlb = (const char*)g_ql_;
        const size_t qrow0 = (size_t)b * T_ + q_start;
#pragma unroll
        for (int mt = 0; mt < 2; mt++)
#pragma unroll
            for (int p4 = 0; p4 < 4; p4++) {
                int roff = mt * 16 + g + ((p4 & 1) << 3);
                int hoff = tig * 2 + ((p4 >> 1) << 3);
                size_t off = (qrow0 + roff) * 32 + hoff * 2;
                qh[mt][p4] = *(const unsigned*)(qhb + off);
                ql[mt][p4] = *(const unsigned*)(qlb + off);
            }
    }

    float Do[2][2][4];
#pragma unroll
    for (int a = 0; a < 2; a++)
#pragma unroll
        for (int c = 0; c < 2; c++)
#pragma unroll
            for (int e = 0; e < 4; e++) Do[a][c][e] = 0.f;
    float l[2][2] = {{0.f, 0.f}, {0.f, 0.f}};

    char* wb = sbuf + w * 9216;
    const __half* khg = (const __half*)g_kh_ + (size_t)b * T_ * 16;
    const __half* klg = (const __half*)g_kl_ + (size_t)b * T_ * 16;
    const __half* vhg = (const __half*)g_vh_ + (size_t)b * 16 * T_;
    const __half* vlg = (const __half*)g_vl_ + (size_t)b * 16 * T_;

    auto load_chunk = [&](int bf, int t0) {
        unsigned sa = (unsigned)__cvta_generic_to_shared(wb + bf * 3072);
        const int e = lane >> 1;
        const int hf = lane & 1;
        cp16(sa +        (unsigned)(e * 48 + hf * 16), khg + (size_t)(t0 + e) * 16 + hf * 8);
        cp16(sa + 768u  + (unsigned)(e * 48 + hf * 16), klg + (size_t)(t0 + e) * 16 + hf * 8);
        cp16(sa + 1536u + (unsigned)(e * 48 + hf * 16), vhg + (size_t)e * T_ + t0 + hf * 8);
        cp16(sa + 2304u + (unsigned)(e * 48 + hf * 16), vlg + (size_t)e * T_ + t0 + hf * 8);
        asm volatile("cp.async.commit_group;");
    };

    auto compute = [&](int bf, int t0, bool masked) {
        const char* kh_s = wb + bf * 3072;
        const char* kl_s = kh_s + 768;
        const char* vh_s = kh_s + 1536;
        const char* vl_s = kh_s + 2304;

        unsigned khb[2][2], klb[2][2], vhb[2][2], vlb[2][2];
#pragma unroll
        for (int nt = 0; nt < 2; nt++) {
            int key = g + nt * 8;
            khb[nt][0] = *(const unsigned*)(kh_s + key * 48 + tig * 4);
            khb[nt][1] = *(const unsigned*)(kh_s + key * 48 + 16 + tig * 4);
            klb[nt][0] = *(const unsigned*)(kl_s + key * 48 + tig * 4);
            klb[nt][1] = *(const unsigned*)(kl_s + key * 48 + 16 + tig * 4);
            int h = g + nt * 8;
            vhb[nt][0] = *(const unsigned*)(vh_s + h * 48 + tig * 4);
            vhb[nt][1] = *(const unsigned*)(vh_s + h * 48 + 16 + tig * 4);
            vlb[nt][0] = *(const unsigned*)(vl_s + h * 48 + tig * 4);
            vlb[nt][1] = *(const unsigned*)(vl_s + h * 48 + 16 + tig * 4);
        }

#pragma unroll
        for (int mt = 0; mt < 2; mt++) {
            float ds[2][4];
#pragma unroll
            for (int nt = 0; nt < 2; nt++) {
#pragma unroll
                for (int e = 0; e < 4; e++) ds[nt][e] = 0.f;
                mma16816(ds[nt], qh[mt], khb[nt]);
                mma16816(ds[nt], qh[mt], klb[nt]);
                mma16816(ds[nt], ql[mt], khb[nt]);
            }
            const int rowq0 = q_start + mt * 16 + g;
#pragma unroll
            for (int nt = 0; nt < 2; nt++) {
                const int kc = t0 + nt * 8 + 2 * tig;
#pragma unroll
                for (int e = 0; e < 4; e++) {
                    float p = ex2(ds[nt][e]);
                    if (masked) {
                        int key = kc + (e & 1);
                        int rq  = rowq0 + ((e >> 1) << 3);
                        p = (key <= rq) ? p : 0.f;
                    }
                    ds[nt][e] = p;
                    l[mt][e >> 1] += p;
                }
            }
            unsigned pa[4];
            pa[0] = packh2(ds[0][1], ds[0][0]);
            pa[1] = packh2(ds[0][3], ds[0][2]);
            pa[2] = packh2(ds[1][1], ds[1][0]);
            pa[3] = packh2(ds[1][3], ds[1][2]);
#pragma unroll
            for (int nh = 0; nh < 2; nh++) {
                mma16816(Do[mt][nh], pa, vhb[nh]);
                mma16816(Do[mt][nh], pa, vlb[nh]);
            }
        }
    };

    // ---- 3-stage per-warp pipeline (stride = 4 warps x 16 keys) ----
    int t0 = kb + w * 16;
    if (t0 < ke) {
        int pending = 0;
        load_chunk(0, t0); pending++;
        if (t0 + 64 < ke) { load_chunk(1, t0 + 64); pending++; }
        int bf = 0;
        for (; t0 < ke; t0 += 64, bf = (bf == 2 ? 0 : bf + 1)) {
            if (t0 + 128 < ke) {
                load_chunk((bf + 2) % 3, t0 + 128);
                pending++;
            }
            pending--;
            if (pending >= 2)      asm volatile("cp.async.wait_group 2;");
            else if (pending == 1) asm volatile("cp.async.wait_group 1;");
            else                   asm volatile("cp.async.wait_group 0;");
            __syncwarp();
            compute(bf, t0, t0 >= q_start);
            __syncwarp();
        }
    }

    // quad reduce row sums
#pragma unroll
    for (int off = 1; off <= 2; off <<= 1)
#pragma unroll
        for (int mt = 0; mt < 2; mt++) {
            l[mt][0] += __shfl_xor_sync(0xffffffffu, l[mt][0], off);
            l[mt][1] += __shfl_xor_sync(0xffffffffu, l[mt][1], off);
        }

    // in-block reduction across the 4 warps
    __syncthreads();
    float* sred = (float*)sbuf;            // [4][32][16]
    float* sl   = (float*)(sbuf + 8192);   // [4][32]
#pragma unroll
    for (int mt = 0; mt < 2; mt++) {
#pragma unroll
        for (int nt = 0; nt < 2; nt++)
#pragma unroll
            for (int e = 0; e < 4; e++) {
                int rl = mt * 16 + g + ((e >> 1) << 3);
                int cl = nt * 8 + tig * 2 + (e & 1);
                sred[(w * 32 + rl) * 16 + cl] = Do[mt][nt][e];
            }
        if (tig == 0) {
            sl[w * 32 + mt * 16 + g]     = l[mt][0];
            sl[w * 32 + mt * 16 + g + 8] = l[mt][1];
        }
    }
    __syncthreads();

    {
        const int row = tid >> 2;
        const int cg  = tid & 3;
        float4 a = make_float4(0.f, 0.f, 0.f, 0.f);
#pragma unroll
        for (int ww = 0; ww < 4; ww++) {
            float4 t = *(const float4*)&sred[(ww * 32 + row) * 16 + cg * 4];
            a.x += t.x; a.y += t.y; a.z += t.z; a.w += t.w;
        }
        const size_t prow = (size_t)split * BT_ + (size_t)b * T_ + q_start + row;
        ((float4*)(g_pacc + prow * 16))[cg] = a;
        if (cg == 0) {
            float ls = sl[row] + sl[32 + row] + sl[64 + row] + sl[96 + row];
            g_pl[prow] = ls;
        }
    }
}

// ---------------------------------------------------------------------------
// Kernel 3: combine 4 split slots. 4 threads/row, 128-thread blocks.
// ---------------------------------------------------------------------------
__global__ __launch_bounds__(128)
void combine_kernel(float* __restrict__ out) {
    const int idx = blockIdx.x * 128 + threadIdx.x;
    const int row = idx >> 2;
    const int cg  = idx & 3;

    float l = 0.f;
#pragma unroll
    for (int s = 0; s < SPLITS; s++) l += g_pl[(size_t)s * BT_ + row];
    const float inv = 1.0f / l;

    float4 a = make_float4(0.f, 0.f, 0.f, 0.f);
#pragma unroll
    for (int s = 0; s < SPLITS; s++) {
        float4 t = ((const float4*)(g_pacc + ((size_t)s * BT_ + row) * 16))[cg];
        a.x += t.x; a.y += t.y; a.z += t.z; a.w += t.w;
    }
    ((float4*)(out + (size_t)row * 16))[cg] =
        make_float4(a.x * inv, a.y * inv, a.z * inv, a.w * inv);
}

extern "C" void kernel_launch(void* const* d_in, const int* in_sizes, int n_in,
                              void* d_out, int out_size) {
    const float* x  = (const float*)d_in[0];
    const float* Wk = (const float*)d_in[1];
    const float* Wq = (const float*)d_in[2];
    const float* Wv = (const float*)d_in[3];
    float* out = (float*)d_out;

    prep_kernel<<<144, 256>>>(Wk, Wq, Wv);
    proj_mma<<<BT_ / 64, 128>>>(x);
    attn_kernel<<<dim3(T_ / 32, SPLITS, B_), 128>>>();
    combine_kernel<<<BT_ * 4 / 128, 128>>>(out);
}